// round 1
// baseline (speedup 1.0000x reference)
#include <cuda_runtime.h>
#include <cstdint>

#define NU 100000
#define NI 20000
#define NE 250000
#define H  128
#define HEADS 2
#define D  64

// ---------------- scratch (static device arrays; no allocation) ----------------
__device__ float g_zu [NU * H];
__device__ float g_zi [NI * H];
__device__ float g_zu2[NU * H];
__device__ float g_zi2[NI * H];
__device__ float g_xl [NU * H];   // source-side projection (max NU rows)
__device__ float g_xr [NU * H];   // target-side projection (max NU rows)
__device__ float g_p  [NE * HEADS];
__device__ float g_den[NU * HEADS];

// ---------------- generic fp32 GEMM: C[M,N] = A[M,K] @ W[K,N] + bias[N] -------
// 128x128 block tile, 8x8 per thread, BK=8, 256 threads.
__global__ __launch_bounds__(256) void sgemm_bias(
    const float* __restrict__ A, const float* __restrict__ W,
    const float* __restrict__ bias, float* __restrict__ C,
    int M, int N, int K)
{
    __shared__ float As[8][132];
    __shared__ float Bs[8][132];

    const int bm = blockIdx.y * 128;
    const int bn = blockIdx.x * 128;
    const int tid = threadIdx.x;
    const int tx = tid & 15;     // n-dir (8 cols each)
    const int ty = tid >> 4;     // m-dir (8 rows each)

    float acc[8][8];
#pragma unroll
    for (int i = 0; i < 8; i++)
#pragma unroll
        for (int j = 0; j < 8; j++) acc[i][j] = 0.f;

    const int ar = tid >> 1;           // 0..127 row within tile
    const int ak = (tid & 1) * 4;      // 0 or 4
    const int br = tid >> 5;           // 0..7   k row
    const int bc = (tid & 31) * 4;     // 0..124 col

    for (int k0 = 0; k0 < K; k0 += 8) {
        float4 av = make_float4(0.f, 0.f, 0.f, 0.f);
        if (bm + ar < M)
            av = *(const float4*)(A + (size_t)(bm + ar) * K + k0 + ak);
        As[ak + 0][ar] = av.x;
        As[ak + 1][ar] = av.y;
        As[ak + 2][ar] = av.z;
        As[ak + 3][ar] = av.w;

        float4 bv = *(const float4*)(W + (size_t)(k0 + br) * N + bn + bc);
        *(float4*)(&Bs[br][bc]) = bv;
        __syncthreads();

#pragma unroll
        for (int k = 0; k < 8; k++) {
            float a[8], b[8];
            *(float4*)(a)     = *(const float4*)(&As[k][ty * 8]);
            *(float4*)(a + 4) = *(const float4*)(&As[k][ty * 8 + 4]);
            *(float4*)(b)     = *(const float4*)(&Bs[k][tx * 8]);
            *(float4*)(b + 4) = *(const float4*)(&Bs[k][tx * 8 + 4]);
#pragma unroll
            for (int i = 0; i < 8; i++)
#pragma unroll
                for (int j = 0; j < 8; j++)
                    acc[i][j] += a[i] * b[j];
        }
        __syncthreads();
    }

#pragma unroll
    for (int i = 0; i < 8; i++) {
        int row = bm + ty * 8 + i;
        if (row >= M) continue;
        float* cp = C + (size_t)row * N + bn + tx * 8;
        const float* bp = bias + bn + tx * 8;
#pragma unroll
        for (int j = 0; j < 8; j += 4) {
            float4 v;
            v.x = acc[i][j + 0] + bp[j + 0];
            v.y = acc[i][j + 1] + bp[j + 1];
            v.z = acc[i][j + 2] + bp[j + 2];
            v.w = acc[i][j + 3] + bp[j + 3];
            *(float4*)(cp + j) = v;
        }
    }
}

// ---------------- helpers -----------------------------------------------------
__global__ void zero_f32(float* __restrict__ p, int n) {
    int i = blockIdx.x * blockDim.x + threadIdx.x;
    if (i < n) p[i] = 0.f;
}

// out[r, :] = bias[:]  (H columns)
__global__ void init_rows_bias(float* __restrict__ out, const float* __restrict__ bias, int n_rows) {
    int i = blockIdx.x * blockDim.x + threadIdx.x;
    if (i < n_rows * H) out[i] = bias[i & (H - 1)];
}

__global__ void relu_inplace(float* __restrict__ p, int n) {
    int i = blockIdx.x * blockDim.x + threadIdx.x;
    if (i < n) p[i] = fmaxf(p[i], 0.f);
}

// ---------------- edge pass 1: unnormalized softmax weights -------------------
// warp per edge. lane covers elements [lane*4, lane*4+4). lanes 0-15 = head 0,
// lanes 16-31 = head 1. p[e,h] = exp( sum_d leaky(xl[s]+xr[t]) * att ),
// den[t,h] += p[e,h].
__global__ __launch_bounds__(256) void edge_logits(
    const float* __restrict__ xl, const float* __restrict__ xr,
    const int* __restrict__ sidx, const int* __restrict__ didx,
    const float* __restrict__ att,
    float* __restrict__ p, float* __restrict__ den, int nE)
{
    int w = (blockIdx.x * blockDim.x + threadIdx.x) >> 5;
    if (w >= nE) return;
    int lane = threadIdx.x & 31;
    int s = sidx[w], t = didx[w];

    float4 a  = *(const float4*)(xl + (size_t)s * H + lane * 4);
    float4 b  = *(const float4*)(xr + (size_t)t * H + lane * 4);
    float4 av = *(const float4*)(att + lane * 4);

    float e0 = a.x + b.x; e0 = (e0 > 0.f) ? e0 : 0.2f * e0;
    float e1 = a.y + b.y; e1 = (e1 > 0.f) ? e1 : 0.2f * e1;
    float e2 = a.z + b.z; e2 = (e2 > 0.f) ? e2 : 0.2f * e2;
    float e3 = a.w + b.w; e3 = (e3 > 0.f) ? e3 : 0.2f * e3;

    float s0 = e0 * av.x + e1 * av.y + e2 * av.z + e3 * av.w;
#pragma unroll
    for (int o = 8; o > 0; o >>= 1)
        s0 += __shfl_xor_sync(0xffffffffu, s0, o);

    if ((lane & 15) == 0) {
        int h = lane >> 4;
        float pe = expf(s0);
        p[(size_t)w * HEADS + h] = pe;
        atomicAdd(den + (size_t)t * HEADS + h, pe);
    }
}

// ---------------- edge pass 2: weighted scatter --------------------------------
__global__ __launch_bounds__(256) void edge_scatter(
    const float* __restrict__ xl,
    const int* __restrict__ sidx, const int* __restrict__ didx,
    const float* __restrict__ p, const float* __restrict__ den,
    float* __restrict__ out, int nE)
{
    int w = (blockIdx.x * blockDim.x + threadIdx.x) >> 5;
    if (w >= nE) return;
    int lane = threadIdx.x & 31;
    int s = sidx[w], t = didx[w];
    int h = lane >> 4;

    float alpha = p[(size_t)w * HEADS + h] / (den[(size_t)t * HEADS + h] + 1e-16f);
    float4 v = *(const float4*)(xl + (size_t)s * H + lane * 4);
    float* o = out + (size_t)t * H + lane * 4;
    atomicAdd(o + 0, v.x * alpha);
    atomicAdd(o + 1, v.y * alpha);
    atomicAdd(o + 2, v.z * alpha);
    atomicAdd(o + 3, v.w * alpha);
}

// ---------------- launch helpers ----------------------------------------------
static inline void launch_gemm(const float* A, const float* W, const float* bias,
                               float* C, int M, int N, int K, cudaStream_t st) {
    dim3 grid((N + 127) / 128, (M + 127) / 128);
    sgemm_bias<<<grid, 256, 0, st>>>(A, W, bias, C, M, N, K);
}

extern "C" void kernel_launch(void* const* d_in, const int* in_sizes, int n_in,
                              void* d_out, int out_size)
{
    const float* x_user  = (const float*)d_in[0];
    const float* x_item  = (const float*)d_in[1];
    const float* Wp_user = (const float*)d_in[2];
    const float* bp_user = (const float*)d_in[3];
    const float* Wp_item = (const float*)d_in[4];
    const float* bp_item = (const float*)d_in[5];
    const float* Wl      = (const float*)d_in[6];   // [L,2,H,H]
    const float* bl      = (const float*)d_in[7];   // [L,2,H]
    const float* Wr      = (const float*)d_in[8];   // [L,2,H,H]
    const float* br      = (const float*)d_in[9];   // [L,2,H]
    const float* att     = (const float*)d_in[10];  // [L,2,HEADS,D]
    const float* bias    = (const float*)d_in[11];  // [L,2,H]
    const int*   e_src   = (const int*)d_in[12];
    const int*   e_dst   = (const int*)d_in[13];
    const int    nE      = in_sizes[12];

    float* out = (float*)d_out;

    float *zu, *zi, *zu2, *zi2, *xl, *xr, *pp, *den;
    cudaGetSymbolAddress((void**)&zu,  g_zu);
    cudaGetSymbolAddress((void**)&zi,  g_zi);
    cudaGetSymbolAddress((void**)&zu2, g_zu2);
    cudaGetSymbolAddress((void**)&zi2, g_zi2);
    cudaGetSymbolAddress((void**)&xl,  g_xl);
    cudaGetSymbolAddress((void**)&xr,  g_xr);
    cudaGetSymbolAddress((void**)&pp,  g_p);
    cudaGetSymbolAddress((void**)&den, g_den);

    cudaStream_t st = 0;  // harness captures the default-stream work

    const int EBLK = (nE * 32 + 255) / 256;

    // ---- input projections ----
    launch_gemm(x_user, Wp_user, bp_user, zu, NU, H, 64, st);
    launch_gemm(x_item, Wp_item, bp_item, zi, NI, H, 128, st);

    for (int l = 0; l < 2; l++) {
        const float* inU = (l == 0) ? zu : zu2;
        const float* inI = (l == 0) ? zi : zi2;
        float* outU = (l == 0) ? zu2 : out;             // zu region of output
        float* outI = (l == 0) ? zi2 : out + (size_t)NU * H;  // zi region

        // ---- relation 0: user -> item (src = e_src users, dst = e_dst items)
        {
            int r = l * 2 + 0;
            launch_gemm(inU, Wl + (size_t)r * H * H, bl + (size_t)r * H, xl, NU, H, H, st);
            launch_gemm(inI, Wr + (size_t)r * H * H, br + (size_t)r * H, xr, NI, H, H, st);
            zero_f32<<<(NI * HEADS + 255) / 256, 256, 0, st>>>(den, NI * HEADS);
            init_rows_bias<<<(NI * H + 255) / 256, 256, 0, st>>>(outI, bias + (size_t)r * H, NI);
            edge_logits<<<EBLK, 256, 0, st>>>(xl, xr, e_src, e_dst, att + (size_t)r * H, pp, den, nE);
            edge_scatter<<<EBLK, 256, 0, st>>>(xl, e_src, e_dst, pp, den, outI, nE);
        }
        // ---- relation 1: item -> user (src = e_dst items, dst = e_src users)
        {
            int r = l * 2 + 1;
            launch_gemm(inI, Wl + (size_t)r * H * H, bl + (size_t)r * H, xl, NI, H, H, st);
            launch_gemm(inU, Wr + (size_t)r * H * H, br + (size_t)r * H, xr, NU, H, H, st);
            zero_f32<<<(NU * HEADS + 255) / 256, 256, 0, st>>>(den, NU * HEADS);
            init_rows_bias<<<(NU * H + 255) / 256, 256, 0, st>>>(outU, bias + (size_t)r * H, NU);
            edge_logits<<<EBLK, 256, 0, st>>>(xl, xr, e_dst, e_src, att + (size_t)r * H, pp, den, nE);
            edge_scatter<<<EBLK, 256, 0, st>>>(xl, e_dst, e_src, pp, den, outU, nE);
        }

        if (l == 0) {
            relu_inplace<<<(NU * H + 255) / 256, 256, 0, st>>>(zu2, NU * H);
            relu_inplace<<<(NI * H + 255) / 256, 256, 0, st>>>(zi2, NI * H);
        }
    }
}

// round 3
// speedup vs baseline: 1.5262x; 1.5262x over previous
#include <cuda_runtime.h>
#include <cstdint>

#define NU 100000
#define NI 20000
#define NE 250000
#define H  128
#define HEADS 2
#define D  64

// ---------------- scratch (static device arrays; no allocation) ----------------
__device__ float g_zu [NU * H];
__device__ float g_zi [NI * H];
__device__ float g_zu2[NU * H];
__device__ float g_zi2[NI * H];
__device__ float g_xlu[NU * H];
__device__ float g_xru[NU * H];
__device__ float g_xli[NI * H];
__device__ float g_xri[NI * H];
__device__ float g_p  [NE * HEADS];
__device__ float g_den[NU * HEADS];

// ---------------- tf32 tensor-core GEMM ---------------------------------------
// C[M,128] = A[M,K] @ W[K,128] + bias  (K % 32 == 0). Dual-weight: blockIdx.x
// selects (W0,b0,C0) or (W1,b1,C1) so independent linears share one launch.
// 128x128x32 tiles, 8 warps (2x4), warp computes 64x32 via m16n8k8 tf32 mma.

#define BM 128
#define BN 128
#define BK 32
#define AST 36    // A smem row stride (floats): conflict-free ldmatrix phases
#define BST 136   // B smem row stride (floats): conflict-free b-frag LDS

__device__ __forceinline__ uint32_t f2tf32(float x) {
    uint32_t u;
    asm("cvt.rna.tf32.f32 %0, %1;" : "=r"(u) : "f"(x));
    return u;
}

__global__ __launch_bounds__(256) void mma_gemm_dual(
    const float* __restrict__ A, int M, int K,
    const float* __restrict__ W0, const float* __restrict__ bv0, float* __restrict__ C0,
    const float* __restrict__ W1, const float* __restrict__ bv1, float* __restrict__ C1)
{
    const float* W  = (blockIdx.x == 0) ? W0  : W1;
    const float* bv = (blockIdx.x == 0) ? bv0 : bv1;
    float*       C  = (blockIdx.x == 0) ? C0  : C1;

    __shared__ float As[BM * AST];
    __shared__ float Bs[BK * BST];

    const int tid  = threadIdx.x;
    const int lane = tid & 31;
    const int warp = tid >> 5;
    const int wm   = warp >> 2;       // 0..1 (64 rows each)
    const int wn   = warp & 3;        // 0..3 (32 cols each)
    const int bm   = blockIdx.y * BM;

    float acc[4][4][4];
#pragma unroll
    for (int mt = 0; mt < 4; mt++)
#pragma unroll
        for (int nt = 0; nt < 4; nt++)
#pragma unroll
            for (int c = 0; c < 4; c++) acc[mt][nt][c] = 0.f;

    for (int k0 = 0; k0 < K; k0 += BK) {
        // stage A tile [128 x 32] (tf32-rounded)
#pragma unroll
        for (int i = 0; i < 4; i++) {
            int idx = tid + 256 * i;
            int row = idx >> 3;
            int col = (idx & 7) * 4;
            float4 v = make_float4(0.f, 0.f, 0.f, 0.f);
            if (bm + row < M)
                v = *(const float4*)(A + (size_t)(bm + row) * K + k0 + col);
            float* dst = As + row * AST + col;
            dst[0] = __uint_as_float(f2tf32(v.x));
            dst[1] = __uint_as_float(f2tf32(v.y));
            dst[2] = __uint_as_float(f2tf32(v.z));
            dst[3] = __uint_as_float(f2tf32(v.w));
        }
        // stage B tile [32 x 128] (tf32-rounded), row-major [k][n]
#pragma unroll
        for (int i = 0; i < 4; i++) {
            int idx = tid + 256 * i;
            int kr  = idx >> 5;
            int col = (idx & 31) * 4;
            float4 v = *(const float4*)(W + (size_t)(k0 + kr) * BN + col);
            float4 t;
            t.x = __uint_as_float(f2tf32(v.x));
            t.y = __uint_as_float(f2tf32(v.y));
            t.z = __uint_as_float(f2tf32(v.z));
            t.w = __uint_as_float(f2tf32(v.w));
            *(float4*)(Bs + kr * BST + col) = t;
        }
        __syncthreads();

#pragma unroll
        for (int kk = 0; kk < 4; kk++) {
            // A fragments: 4 m-tiles, ldmatrix.x4 each (b16 view of fp32 8x4 blocks)
            uint32_t a[4][4];
            {
                int row  = wm * 64 + (lane & 15);
                int koff = kk * 8 + ((lane >> 4) << 2);
#pragma unroll
                for (int mt = 0; mt < 4; mt++) {
                    uint32_t saddr = (uint32_t)__cvta_generic_to_shared(
                        As + (row + mt * 16) * AST + koff);
                    asm volatile(
                        "ldmatrix.sync.aligned.m8n8.x4.shared.b16 {%0,%1,%2,%3}, [%4];"
                        : "=r"(a[mt][0]), "=r"(a[mt][1]), "=r"(a[mt][2]), "=r"(a[mt][3])
                        : "r"(saddr));
                }
            }
            // B fragments: 4 n-tiles, 2 scalar LDS each (conflict-free w/ BST=136)
            uint32_t b[4][2];
            {
                int kb = kk * 8 + (lane & 3);
                int nb = wn * 32 + (lane >> 2);
#pragma unroll
                for (int nt = 0; nt < 4; nt++) {
                    b[nt][0] = __float_as_uint(Bs[kb * BST + nb + nt * 8]);
                    b[nt][1] = __float_as_uint(Bs[(kb + 4) * BST + nb + nt * 8]);
                }
            }
#pragma unroll
            for (int mt = 0; mt < 4; mt++)
#pragma unroll
                for (int nt = 0; nt < 4; nt++) {
                    asm volatile(
                        "mma.sync.aligned.m16n8k8.row.col.f32.tf32.tf32.f32 "
                        "{%0,%1,%2,%3}, {%4,%5,%6,%7}, {%8,%9}, {%0,%1,%2,%3};"
                        : "+f"(acc[mt][nt][0]), "+f"(acc[mt][nt][1]),
                          "+f"(acc[mt][nt][2]), "+f"(acc[mt][nt][3])
                        : "r"(a[mt][0]), "r"(a[mt][1]), "r"(a[mt][2]), "r"(a[mt][3]),
                          "r"(b[nt][0]), "r"(b[nt][1]));
                }
        }
        __syncthreads();
    }

    // epilogue: bias add + store (c0,c1 contiguous -> float2)
    const int r0 = bm + wm * 64 + (lane >> 2);
    const int cb = wn * 32 + 2 * (lane & 3);
#pragma unroll
    for (int mt = 0; mt < 4; mt++) {
#pragma unroll
        for (int nt = 0; nt < 4; nt++) {
            int row = r0 + mt * 16;
            int col = cb + nt * 8;
            float bx = bv[col], by = bv[col + 1];
            if (row < M) {
                float2 v = make_float2(acc[mt][nt][0] + bx, acc[mt][nt][1] + by);
                *(float2*)(C + (size_t)row * BN + col) = v;
            }
            if (row + 8 < M) {
                float2 v = make_float2(acc[mt][nt][2] + bx, acc[mt][nt][3] + by);
                *(float2*)(C + (size_t)(row + 8) * BN + col) = v;
            }
        }
    }
}

// ---------------- helpers -----------------------------------------------------
__global__ void zero_f32(float* __restrict__ p, int n) {
    int i = blockIdx.x * blockDim.x + threadIdx.x;
    if (i < n) p[i] = 0.f;
}

__global__ void init_rows_bias(float* __restrict__ out, const float* __restrict__ bias, int n_rows) {
    int i = blockIdx.x * blockDim.x + threadIdx.x;
    if (i < n_rows * H) out[i] = bias[i & (H - 1)];
}

__global__ void relu_inplace(float* __restrict__ p, int n) {
    int i = blockIdx.x * blockDim.x + threadIdx.x;
    if (i < n) p[i] = fmaxf(p[i], 0.f);
}

// ---------------- edge pass 1: unnormalized softmax weights -------------------
__global__ __launch_bounds__(256) void edge_logits(
    const float* __restrict__ xl, const float* __restrict__ xr,
    const int* __restrict__ sidx, const int* __restrict__ didx,
    const float* __restrict__ att,
    float* __restrict__ p, float* __restrict__ den, int nE)
{
    int w = (blockIdx.x * blockDim.x + threadIdx.x) >> 5;
    if (w >= nE) return;
    int lane = threadIdx.x & 31;
    int s = sidx[w], t = didx[w];

    float4 a  = *(const float4*)(xl + (size_t)s * H + lane * 4);
    float4 b  = *(const float4*)(xr + (size_t)t * H + lane * 4);
    float4 av = *(const float4*)(att + lane * 4);

    float e0 = a.x + b.x; e0 = (e0 > 0.f) ? e0 : 0.2f * e0;
    float e1 = a.y + b.y; e1 = (e1 > 0.f) ? e1 : 0.2f * e1;
    float e2 = a.z + b.z; e2 = (e2 > 0.f) ? e2 : 0.2f * e2;
    float e3 = a.w + b.w; e3 = (e3 > 0.f) ? e3 : 0.2f * e3;

    float s0 = e0 * av.x + e1 * av.y + e2 * av.z + e3 * av.w;
#pragma unroll
    for (int o = 8; o > 0; o >>= 1)
        s0 += __shfl_xor_sync(0xffffffffu, s0, o);

    if ((lane & 15) == 0) {
        int h = lane >> 4;
        float pe = expf(s0);
        p[(size_t)w * HEADS + h] = pe;
        atomicAdd(den + (size_t)t * HEADS + h, pe);
    }
}

// ---------------- edge pass 2: weighted scatter --------------------------------
__global__ __launch_bounds__(256) void edge_scatter(
    const float* __restrict__ xl,
    const int* __restrict__ sidx, const int* __restrict__ didx,
    const float* __restrict__ p, const float* __restrict__ den,
    float* __restrict__ out, int nE)
{
    int w = (blockIdx.x * blockDim.x + threadIdx.x) >> 5;
    if (w >= nE) return;
    int lane = threadIdx.x & 31;
    int s = sidx[w], t = didx[w];
    int h = lane >> 4;

    float alpha = p[(size_t)w * HEADS + h] / (den[(size_t)t * HEADS + h] + 1e-16f);
    float4 v = *(const float4*)(xl + (size_t)s * H + lane * 4);
    float* o = out + (size_t)t * H + lane * 4;
    atomicAdd(o + 0, v.x * alpha);
    atomicAdd(o + 1, v.y * alpha);
    atomicAdd(o + 2, v.z * alpha);
    atomicAdd(o + 3, v.w * alpha);
}

// ---------------- launchers ----------------------------------------------------
static inline void launch_gemm1(const float* A, int M, int K,
                                const float* W, const float* bias, float* C,
                                cudaStream_t st) {
    dim3 grid(1, (M + BM - 1) / BM);
    mma_gemm_dual<<<grid, 256, 0, st>>>(A, M, K, W, bias, C, W, bias, C);
}

static inline void launch_gemm2(const float* A, int M, int K,
                                const float* W0, const float* b0, float* C0,
                                const float* W1, const float* b1, float* C1,
                                cudaStream_t st) {
    dim3 grid(2, (M + BM - 1) / BM);
    mma_gemm_dual<<<grid, 256, 0, st>>>(A, M, K, W0, b0, C0, W1, b1, C1);
}

extern "C" void kernel_launch(void* const* d_in, const int* in_sizes, int n_in,
                              void* d_out, int out_size)
{
    const float* x_user  = (const float*)d_in[0];
    const float* x_item  = (const float*)d_in[1];
    const float* Wp_user = (const float*)d_in[2];
    const float* bp_user = (const float*)d_in[3];
    const float* Wp_item = (const float*)d_in[4];
    const float* bp_item = (const float*)d_in[5];
    const float* Wl      = (const float*)d_in[6];   // [L,2,H,H]
    const float* bl      = (const float*)d_in[7];   // [L,2,H]
    const float* Wr      = (const float*)d_in[8];   // [L,2,H,H]
    const float* br      = (const float*)d_in[9];   // [L,2,H]
    const float* att     = (const float*)d_in[10];  // [L,2,HEADS,D]
    const float* bias    = (const float*)d_in[11];  // [L,2,H]
    const int*   e_src   = (const int*)d_in[12];
    const int*   e_dst   = (const int*)d_in[13];
    const int    nE      = in_sizes[12];

    float* out = (float*)d_out;

    float *zu, *zi, *zu2, *zi2, *xlu, *xru, *xli, *xri, *pp, *den;
    cudaGetSymbolAddress((void**)&zu,  g_zu);
    cudaGetSymbolAddress((void**)&zi,  g_zi);
    cudaGetSymbolAddress((void**)&zu2, g_zu2);
    cudaGetSymbolAddress((void**)&zi2, g_zi2);
    cudaGetSymbolAddress((void**)&xlu, g_xlu);
    cudaGetSymbolAddress((void**)&xru, g_xru);
    cudaGetSymbolAddress((void**)&xli, g_xli);
    cudaGetSymbolAddress((void**)&xri, g_xri);
    cudaGetSymbolAddress((void**)&pp,  g_p);
    cudaGetSymbolAddress((void**)&den, g_den);

    cudaStream_t st = 0;
    const int EBLK = (nE * 32 + 255) / 256;
    const size_t HH = (size_t)H * H;

    // ---- input projections ----
    launch_gemm1(x_user, NU, 64,  Wp_user, bp_user, zu, st);
    launch_gemm1(x_item, NI, 128, Wp_item, bp_item, zi, st);

    for (int l = 0; l < 2; l++) {
        const float* inU = (l == 0) ? zu : zu2;
        const float* inI = (l == 0) ? zi : zi2;
        float* outU = (l == 0) ? zu2 : out;
        float* outI = (l == 0) ? zi2 : out + (size_t)NU * H;

        int r0 = l * 2 + 0;   // user -> item
        int r1 = l * 2 + 1;   // item -> user

        // user rows: xl for rel0, xr for rel1 (one launch)
        launch_gemm2(inU, NU, H,
                     Wl + r0 * HH, bl + (size_t)r0 * H, xlu,
                     Wr + r1 * HH, br + (size_t)r1 * H, xru, st);
        // item rows: xr for rel0, xl for rel1 (one launch)
        launch_gemm2(inI, NI, H,
                     Wr + r0 * HH, br + (size_t)r0 * H, xri,
                     Wl + r1 * HH, bl + (size_t)r1 * H, xli, st);

        // ---- relation 0: user -> item ----
        zero_f32<<<(NI * HEADS + 255) / 256, 256, 0, st>>>(den, NI * HEADS);
        init_rows_bias<<<(NI * H + 255) / 256, 256, 0, st>>>(outI, bias + (size_t)r0 * H, NI);
        edge_logits<<<EBLK, 256, 0, st>>>(xlu, xri, e_src, e_dst, att + (size_t)r0 * H, pp, den, nE);
        edge_scatter<<<EBLK, 256, 0, st>>>(xlu, e_src, e_dst, pp, den, outI, nE);

        // ---- relation 1: item -> user ----
        zero_f32<<<(NU * HEADS + 255) / 256, 256, 0, st>>>(den, NU * HEADS);
        init_rows_bias<<<(NU * H + 255) / 256, 256, 0, st>>>(outU, bias + (size_t)r1 * H, NU);
        edge_logits<<<EBLK, 256, 0, st>>>(xli, xru, e_dst, e_src, att + (size_t)r1 * H, pp, den, nE);
        edge_scatter<<<EBLK, 256, 0, st>>>(xli, e_dst, e_src, pp, den, outU, nE);

        if (l == 0) {
            relu_inplace<<<(NU * H + 255) / 256, 256, 0, st>>>(zu2, NU * H);
            relu_inplace<<<(NI * H + 255) / 256, 256, 0, st>>>(zi2, NI * H);
        }
    }
}

// round 4
// speedup vs baseline: 2.1843x; 1.4312x over previous
#include <cuda_runtime.h>
#include <cstdint>

#define NU 100000
#define NI 20000
#define NE 250000
#define H  128
#define HEADS 2
#define D  64

// ---------------- scratch (static device arrays; no allocation) ----------------
__device__ float g_zu [NU * H];
__device__ float g_zi [NI * H];
__device__ float g_zu2[NU * H];
__device__ float g_zi2[NI * H];
__device__ float g_xlu[NU * H];
__device__ float g_xru[NU * H];
__device__ float g_xli[NI * H];
__device__ float g_xri[NI * H];
__device__ float g_p  [NE * HEADS];
__device__ float g_den[NU * HEADS];

// ---------------- tf32 tensor-core GEMM, cp.async 2-stage pipeline -------------
// C[M,128] = A[M,K] @ W[K,128] + bias.  Fused over two row-sections (user rows,
// item rows) x two weight sets (blockIdx.x), so one launch covers 4 linears.
// 128x128x32 tiles, 8 warps (2x4), warp = 64x32 via m16n8k8 tf32 mma.
// tf32 rounding (cvt.rna) applied on fragment registers -> numerics identical
// to smem-side rounding. Optional fused ReLU on A (inter-layer activation).

#define BM 128
#define BN 128
#define BK 32
#define AST 36    // A smem row stride (floats): conflict-free ldmatrix phases
#define BST 136   // B smem row stride (floats): conflict-free b-frag LDS
#define SMEM_BYTES ((2*BM*AST + 2*BK*BST) * 4)

__device__ __forceinline__ uint32_t f2tf32(float x) {
    uint32_t u;
    asm("cvt.rna.tf32.f32 %0, %1;" : "=r"(u) : "f"(x));
    return u;
}

__device__ __forceinline__ void cp16(uint32_t dst, const float* src, bool pred) {
    asm volatile("cp.async.ca.shared.global [%0], [%1], 16, %2;"
                 :: "r"(dst), "l"(src), "r"(pred ? 16 : 0));
}

__global__ __launch_bounds__(256, 2) void gemm_fused(
    const float* __restrict__ Au, int Mu, int Ku,
    const float* __restrict__ Ai, int Mi, int Ki, int UB,
    const float* __restrict__ W00, const float* __restrict__ b00, float* __restrict__ C00,
    const float* __restrict__ W01, const float* __restrict__ b01, float* __restrict__ C01,
    const float* __restrict__ W10, const float* __restrict__ b10, float* __restrict__ C10,
    const float* __restrict__ W11, const float* __restrict__ b11, float* __restrict__ C11,
    int reluA)
{
    extern __shared__ float smbuf[];
    const int sec = (blockIdx.y >= (unsigned)UB) ? 1 : 0;
    const float* A = sec ? Ai : Au;
    const int M = sec ? Mi : Mu;
    const int K = sec ? Ki : Ku;
    const int bm = (sec ? (blockIdx.y - UB) : blockIdx.y) * BM;

    const float* W; const float* bv; float* C;
    if (!sec) { if (blockIdx.x == 0) { W=W00; bv=b00; C=C00; } else { W=W01; bv=b01; C=C01; } }
    else      { if (blockIdx.x == 0) { W=W10; bv=b10; C=C10; } else { W=W11; bv=b11; C=C11; } }

    const int tid  = threadIdx.x;
    const int lane = tid & 31;
    const int warp = tid >> 5;
    const int wm   = warp >> 2;       // 0..1 (64 rows each)
    const int wn   = warp & 3;        // 0..3 (32 cols each)

    float* As = smbuf;                 // 2 x [BM x AST]
    float* Bs = smbuf + 2 * BM * AST;  // 2 x [BK x BST]

    const int arow = tid >> 3;         // 0..31 (+32*i)
    const int acol = (tid & 7) * 4;    // 0..28
    const int brow = tid >> 5;         // 0..7  (+8*i)
    const int bcol = (tid & 31) * 4;   // 0..124

    float acc[4][4][4];
#pragma unroll
    for (int mt = 0; mt < 4; mt++)
#pragma unroll
        for (int nt = 0; nt < 4; nt++)
#pragma unroll
            for (int c = 0; c < 4; c++) acc[mt][nt][c] = 0.f;

    const int KT = K / BK;

    auto stage = [&](int kt, int buf) {
#pragma unroll
        for (int i = 0; i < 4; i++) {
            int row = arow + 32 * i;
            bool p = (bm + row) < M;
            int r = p ? (bm + row) : (M - 1);
            uint32_t d = (uint32_t)__cvta_generic_to_shared(As + buf * BM * AST + row * AST + acol);
            cp16(d, A + (size_t)r * K + kt * BK + acol, p);
        }
#pragma unroll
        for (int i = 0; i < 4; i++) {
            int kr = brow + 8 * i;
            uint32_t d = (uint32_t)__cvta_generic_to_shared(Bs + buf * BK * BST + kr * BST + bcol);
            cp16(d, W + (size_t)(kt * BK + kr) * BN + bcol, true);
        }
    };

    auto compute = [&](int buf) {
        const float* Asb = As + buf * BM * AST;
        const float* Bsb = Bs + buf * BK * BST;
#pragma unroll
        for (int kk = 0; kk < 4; kk++) {
            uint32_t a[4][4];
            {
                int row  = wm * 64 + (lane & 15);
                int koff = kk * 8 + ((lane >> 4) << 2);
#pragma unroll
                for (int mt = 0; mt < 4; mt++) {
                    uint32_t sa = (uint32_t)__cvta_generic_to_shared(
                        Asb + (row + mt * 16) * AST + koff);
                    asm volatile(
                        "ldmatrix.sync.aligned.m8n8.x4.shared.b16 {%0,%1,%2,%3}, [%4];"
                        : "=r"(a[mt][0]), "=r"(a[mt][1]), "=r"(a[mt][2]), "=r"(a[mt][3])
                        : "r"(sa));
                }
            }
            if (reluA) {
#pragma unroll
                for (int mt = 0; mt < 4; mt++)
#pragma unroll
                    for (int i = 0; i < 4; i++)
                        a[mt][i] = __float_as_uint(fmaxf(__uint_as_float(a[mt][i]), 0.f));
            }
#pragma unroll
            for (int mt = 0; mt < 4; mt++)
#pragma unroll
                for (int i = 0; i < 4; i++)
                    a[mt][i] = f2tf32(__uint_as_float(a[mt][i]));

            uint32_t b[4][2];
            {
                int kb = kk * 8 + (lane & 3);
                int nb = wn * 32 + (lane >> 2);
#pragma unroll
                for (int nt = 0; nt < 4; nt++) {
                    b[nt][0] = f2tf32(Bsb[kb * BST + nb + nt * 8]);
                    b[nt][1] = f2tf32(Bsb[(kb + 4) * BST + nb + nt * 8]);
                }
            }
#pragma unroll
            for (int mt = 0; mt < 4; mt++)
#pragma unroll
                for (int nt = 0; nt < 4; nt++) {
                    asm volatile(
                        "mma.sync.aligned.m16n8k8.row.col.f32.tf32.tf32.f32 "
                        "{%0,%1,%2,%3}, {%4,%5,%6,%7}, {%8,%9}, {%0,%1,%2,%3};"
                        : "+f"(acc[mt][nt][0]), "+f"(acc[mt][nt][1]),
                          "+f"(acc[mt][nt][2]), "+f"(acc[mt][nt][3])
                        : "r"(a[mt][0]), "r"(a[mt][1]), "r"(a[mt][2]), "r"(a[mt][3]),
                          "r"(b[nt][0]), "r"(b[nt][1]));
                }
        }
    };

    stage(0, 0);
    asm volatile("cp.async.commit_group;");
    for (int kt = 0; kt < KT; kt++) {
        int buf = kt & 1;
        if (kt + 1 < KT) {
            stage(kt + 1, buf ^ 1);
            asm volatile("cp.async.commit_group;");
            asm volatile("cp.async.wait_group 1;");
        } else {
            asm volatile("cp.async.wait_group 0;");
        }
        __syncthreads();
        compute(buf);
        __syncthreads();
    }

    // epilogue: bias add + store
    const int r0 = bm + wm * 64 + (lane >> 2);
    const int cb = wn * 32 + 2 * (lane & 3);
#pragma unroll
    for (int mt = 0; mt < 4; mt++) {
#pragma unroll
        for (int nt = 0; nt < 4; nt++) {
            int row = r0 + mt * 16;
            int col = cb + nt * 8;
            float bx = bv[col], by = bv[col + 1];
            if (row < M) {
                float2 v = make_float2(acc[mt][nt][0] + bx, acc[mt][nt][1] + by);
                *(float2*)(C + (size_t)row * BN + col) = v;
            }
            if (row + 8 < M) {
                float2 v = make_float2(acc[mt][nt][2] + bx, acc[mt][nt][3] + by);
                *(float2*)(C + (size_t)(row + 8) * BN + col) = v;
            }
        }
    }
}

// ---------------- helpers -----------------------------------------------------
__global__ void zero_f32(float* __restrict__ p, int n) {
    int i = blockIdx.x * blockDim.x + threadIdx.x;
    if (i < n) p[i] = 0.f;
}

__global__ void init_rows_bias(float* __restrict__ out, const float* __restrict__ bias, int n_rows) {
    int i = blockIdx.x * blockDim.x + threadIdx.x;
    if (i < n_rows * H) out[i] = bias[i & (H - 1)];
}

// ---------------- edge pass 1: unnormalized softmax weights -------------------
__global__ __launch_bounds__(256) void edge_logits(
    const float* __restrict__ xl, const float* __restrict__ xr,
    const int* __restrict__ sidx, const int* __restrict__ didx,
    const float* __restrict__ att,
    float* __restrict__ p, float* __restrict__ den, int nE)
{
    int w = (blockIdx.x * blockDim.x + threadIdx.x) >> 5;
    if (w >= nE) return;
    int lane = threadIdx.x & 31;
    int s = sidx[w], t = didx[w];

    float4 a  = *(const float4*)(xl + (size_t)s * H + lane * 4);
    float4 b  = *(const float4*)(xr + (size_t)t * H + lane * 4);
    float4 av = *(const float4*)(att + lane * 4);

    float e0 = a.x + b.x; e0 = (e0 > 0.f) ? e0 : 0.2f * e0;
    float e1 = a.y + b.y; e1 = (e1 > 0.f) ? e1 : 0.2f * e1;
    float e2 = a.z + b.z; e2 = (e2 > 0.f) ? e2 : 0.2f * e2;
    float e3 = a.w + b.w; e3 = (e3 > 0.f) ? e3 : 0.2f * e3;

    float s0 = e0 * av.x + e1 * av.y + e2 * av.z + e3 * av.w;
#pragma unroll
    for (int o = 8; o > 0; o >>= 1)
        s0 += __shfl_xor_sync(0xffffffffu, s0, o);

    if ((lane & 15) == 0) {
        int h = lane >> 4;
        float pe = expf(s0);
        p[(size_t)w * HEADS + h] = pe;
        asm volatile("red.global.add.f32 [%0], %1;"
                     :: "l"(den + (size_t)t * HEADS + h), "f"(pe) : "memory");
    }
}

// ---------------- edge pass 2: weighted scatter (vector red) -------------------
__global__ __launch_bounds__(256) void edge_scatter(
    const float* __restrict__ xl,
    const int* __restrict__ sidx, const int* __restrict__ didx,
    const float* __restrict__ p, const float* __restrict__ den,
    float* __restrict__ out, int nE)
{
    int w = (blockIdx.x * blockDim.x + threadIdx.x) >> 5;
    if (w >= nE) return;
    int lane = threadIdx.x & 31;
    int s = sidx[w], t = didx[w];
    int h = lane >> 4;

    float alpha = p[(size_t)w * HEADS + h] / (den[(size_t)t * HEADS + h] + 1e-16f);
    float4 v = *(const float4*)(xl + (size_t)s * H + lane * 4);
    float* o = out + (size_t)t * H + lane * 4;
    asm volatile("red.global.add.v4.f32 [%0], {%1,%2,%3,%4};"
                 :: "l"(o), "f"(v.x * alpha), "f"(v.y * alpha),
                    "f"(v.z * alpha), "f"(v.w * alpha) : "memory");
}

extern "C" void kernel_launch(void* const* d_in, const int* in_sizes, int n_in,
                              void* d_out, int out_size)
{
    const float* x_user  = (const float*)d_in[0];
    const float* x_item  = (const float*)d_in[1];
    const float* Wp_user = (const float*)d_in[2];
    const float* bp_user = (const float*)d_in[3];
    const float* Wp_item = (const float*)d_in[4];
    const float* bp_item = (const float*)d_in[5];
    const float* Wl      = (const float*)d_in[6];   // [L,2,H,H]
    const float* bl      = (const float*)d_in[7];   // [L,2,H]
    const float* Wr      = (const float*)d_in[8];   // [L,2,H,H]
    const float* br      = (const float*)d_in[9];   // [L,2,H]
    const float* att     = (const float*)d_in[10];  // [L,2,HEADS,D]
    const float* bias    = (const float*)d_in[11];  // [L,2,H]
    const int*   e_src   = (const int*)d_in[12];
    const int*   e_dst   = (const int*)d_in[13];
    const int    nE      = in_sizes[12];

    float* out = (float*)d_out;

    float *zu, *zi, *zu2, *zi2, *xlu, *xru, *xli, *xri, *pp, *den;
    cudaGetSymbolAddress((void**)&zu,  g_zu);
    cudaGetSymbolAddress((void**)&zi,  g_zi);
    cudaGetSymbolAddress((void**)&zu2, g_zu2);
    cudaGetSymbolAddress((void**)&zi2, g_zi2);
    cudaGetSymbolAddress((void**)&xlu, g_xlu);
    cudaGetSymbolAddress((void**)&xru, g_xru);
    cudaGetSymbolAddress((void**)&xli, g_xli);
    cudaGetSymbolAddress((void**)&xri, g_xri);
    cudaGetSymbolAddress((void**)&pp,  g_p);
    cudaGetSymbolAddress((void**)&den, g_den);

    cudaFuncSetAttribute(gemm_fused, cudaFuncAttributeMaxDynamicSharedMemorySize, SMEM_BYTES);

    cudaStream_t st = 0;
    const int EBLK = (nE * 32 + 255) / 256;
    const size_t HH = (size_t)H * H;
    const int UB = (NU + BM - 1) / BM;   // 782
    const int IB = (NI + BM - 1) / BM;   // 157

    // ---- input projections (one fused launch, grid.x = 1) ----
    {
        dim3 grid(1, UB + IB);
        gemm_fused<<<grid, 256, SMEM_BYTES, st>>>(
            x_user, NU, 64, x_item, NI, 128, UB,
            Wp_user, bp_user, zu,  Wp_user, bp_user, zu,
            Wp_item, bp_item, zi,  Wp_item, bp_item, zi, 0);
    }

    for (int l = 0; l < 2; l++) {
        const float* inU = (l == 0) ? zu : zu2;
        const float* inI = (l == 0) ? zi : zi2;
        float* outU = (l == 0) ? zu2 : out;
        float* outI = (l == 0) ? zi2 : out + (size_t)NU * H;

        int r0 = l * 2 + 0;   // user -> item
        int r1 = l * 2 + 1;   // item -> user

        // one launch: user rows x {Wl[r0]->xlu, Wr[r1]->xru},
        //             item rows x {Wr[r0]->xri, Wl[r1]->xli}
        // layer 1 applies ReLU to A on load (inter-layer activation)
        {
            dim3 grid(2, UB + IB);
            gemm_fused<<<grid, 256, SMEM_BYTES, st>>>(
                inU, NU, H, inI, NI, H, UB,
                Wl + r0 * HH, bl + (size_t)r0 * H, xlu,
                Wr + r1 * HH, br + (size_t)r1 * H, xru,
                Wr + r0 * HH, br + (size_t)r0 * H, xri,
                Wl + r1 * HH, bl + (size_t)r1 * H, xli,
                (l == 1) ? 1 : 0);
        }

        // ---- relation 0: user -> item ----
        zero_f32<<<(NI * HEADS + 255) / 256, 256, 0, st>>>(den, NI * HEADS);
        init_rows_bias<<<(NI * H + 255) / 256, 256, 0, st>>>(outI, bias + (size_t)r0 * H, NI);
        edge_logits<<<EBLK, 256, 0, st>>>(xlu, xri, e_src, e_dst, att + (size_t)r0 * H, pp, den, nE);
        edge_scatter<<<EBLK, 256, 0, st>>>(xlu, e_src, e_dst, pp, den, outI, nE);

        // ---- relation 1: item -> user ----
        zero_f32<<<(NU * HEADS + 255) / 256, 256, 0, st>>>(den, NU * HEADS);
        init_rows_bias<<<(NU * H + 255) / 256, 256, 0, st>>>(outU, bias + (size_t)r1 * H, NU);
        edge_logits<<<EBLK, 256, 0, st>>>(xli, xru, e_dst, e_src, att + (size_t)r1 * H, pp, den, nE);
        edge_scatter<<<EBLK, 256, 0, st>>>(xli, e_dst, e_src, pp, den, outU, nE);
    }
}

// round 5
// speedup vs baseline: 2.3864x; 1.0925x over previous
#include <cuda_runtime.h>
#include <cstdint>

#define NU 100000
#define NI 20000
#define NE 250000
#define H  128
#define HEADS 2
#define D  64

// ---------------- scratch (static device arrays; no allocation) ----------------
__device__ float g_zu [NU * H];
__device__ float g_zi [NI * H];
__device__ float g_zu2[NU * H];
__device__ float g_zi2[NI * H];
__device__ float g_xlu[NU * H];
__device__ float g_xru[NU * H];
__device__ float g_xli[NI * H];
__device__ float g_xri[NI * H];

// CSR (built once per call; graph identical across layers)
__device__ int g_rp_i [NI + 1];   // row ptr, dst = item
__device__ int g_rp_u [NU + 1];   // row ptr, dst = user
__device__ int g_cnt_i[NI];       // counts, then reused as fill cursors
__device__ int g_cnt_u[NU];
__device__ int g_col_i[NE];       // src user per item-dst slot
__device__ int g_col_u[NE];       // src item per user-dst slot

// ---------------- tf32 tensor-core GEMM, cp.async 2-stage pipeline -------------
#define BM 128
#define BN 128
#define BK 32
#define AST 36
#define BST 136
#define SMEM_BYTES ((2*BM*AST + 2*BK*BST) * 4)

__device__ __forceinline__ uint32_t f2tf32(float x) {
    uint32_t u;
    asm("cvt.rna.tf32.f32 %0, %1;" : "=r"(u) : "f"(x));
    return u;
}

__device__ __forceinline__ void cp16(uint32_t dst, const float* src, bool pred) {
    asm volatile("cp.async.ca.shared.global [%0], [%1], 16, %2;"
                 :: "r"(dst), "l"(src), "r"(pred ? 16 : 0));
}

__global__ __launch_bounds__(256, 2) void gemm_fused(
    const float* __restrict__ Au, int Mu, int Ku,
    const float* __restrict__ Ai, int Mi, int Ki, int UB,
    const float* __restrict__ W00, const float* __restrict__ b00, float* __restrict__ C00,
    const float* __restrict__ W01, const float* __restrict__ b01, float* __restrict__ C01,
    const float* __restrict__ W10, const float* __restrict__ b10, float* __restrict__ C10,
    const float* __restrict__ W11, const float* __restrict__ b11, float* __restrict__ C11,
    int reluA)
{
    extern __shared__ float smbuf[];
    const int sec = (blockIdx.y >= (unsigned)UB) ? 1 : 0;
    const float* A = sec ? Ai : Au;
    const int M = sec ? Mi : Mu;
    const int K = sec ? Ki : Ku;
    const int bm = (sec ? (blockIdx.y - UB) : blockIdx.y) * BM;

    const float* W; const float* bv; float* C;
    if (!sec) { if (blockIdx.x == 0) { W=W00; bv=b00; C=C00; } else { W=W01; bv=b01; C=C01; } }
    else      { if (blockIdx.x == 0) { W=W10; bv=b10; C=C10; } else { W=W11; bv=b11; C=C11; } }

    const int tid  = threadIdx.x;
    const int lane = tid & 31;
    const int warp = tid >> 5;
    const int wm   = warp >> 2;
    const int wn   = warp & 3;

    float* As = smbuf;
    float* Bs = smbuf + 2 * BM * AST;

    const int arow = tid >> 3;
    const int acol = (tid & 7) * 4;
    const int brow = tid >> 5;
    const int bcol = (tid & 31) * 4;

    float acc[4][4][4];
#pragma unroll
    for (int mt = 0; mt < 4; mt++)
#pragma unroll
        for (int nt = 0; nt < 4; nt++)
#pragma unroll
            for (int c = 0; c < 4; c++) acc[mt][nt][c] = 0.f;

    const int KT = K / BK;

    auto stage = [&](int kt, int buf) {
#pragma unroll
        for (int i = 0; i < 4; i++) {
            int row = arow + 32 * i;
            bool p = (bm + row) < M;
            int r = p ? (bm + row) : (M - 1);
            uint32_t d = (uint32_t)__cvta_generic_to_shared(As + buf * BM * AST + row * AST + acol);
            cp16(d, A + (size_t)r * K + kt * BK + acol, p);
        }
#pragma unroll
        for (int i = 0; i < 4; i++) {
            int kr = brow + 8 * i;
            uint32_t d = (uint32_t)__cvta_generic_to_shared(Bs + buf * BK * BST + kr * BST + bcol);
            cp16(d, W + (size_t)(kt * BK + kr) * BN + bcol, true);
        }
    };

    auto compute = [&](int buf) {
        const float* Asb = As + buf * BM * AST;
        const float* Bsb = Bs + buf * BK * BST;
#pragma unroll
        for (int kk = 0; kk < 4; kk++) {
            uint32_t a[4][4];
            {
                int row  = wm * 64 + (lane & 15);
                int koff = kk * 8 + ((lane >> 4) << 2);
#pragma unroll
                for (int mt = 0; mt < 4; mt++) {
                    uint32_t sa = (uint32_t)__cvta_generic_to_shared(
                        Asb + (row + mt * 16) * AST + koff);
                    asm volatile(
                        "ldmatrix.sync.aligned.m8n8.x4.shared.b16 {%0,%1,%2,%3}, [%4];"
                        : "=r"(a[mt][0]), "=r"(a[mt][1]), "=r"(a[mt][2]), "=r"(a[mt][3])
                        : "r"(sa));
                }
            }
            if (reluA) {
#pragma unroll
                for (int mt = 0; mt < 4; mt++)
#pragma unroll
                    for (int i = 0; i < 4; i++)
                        a[mt][i] = __float_as_uint(fmaxf(__uint_as_float(a[mt][i]), 0.f));
            }
#pragma unroll
            for (int mt = 0; mt < 4; mt++)
#pragma unroll
                for (int i = 0; i < 4; i++)
                    a[mt][i] = f2tf32(__uint_as_float(a[mt][i]));

            uint32_t b[4][2];
            {
                int kb = kk * 8 + (lane & 3);
                int nb = wn * 32 + (lane >> 2);
#pragma unroll
                for (int nt = 0; nt < 4; nt++) {
                    b[nt][0] = f2tf32(Bsb[kb * BST + nb + nt * 8]);
                    b[nt][1] = f2tf32(Bsb[(kb + 4) * BST + nb + nt * 8]);
                }
            }
#pragma unroll
            for (int mt = 0; mt < 4; mt++)
#pragma unroll
                for (int nt = 0; nt < 4; nt++) {
                    asm volatile(
                        "mma.sync.aligned.m16n8k8.row.col.f32.tf32.tf32.f32 "
                        "{%0,%1,%2,%3}, {%4,%5,%6,%7}, {%8,%9}, {%0,%1,%2,%3};"
                        : "+f"(acc[mt][nt][0]), "+f"(acc[mt][nt][1]),
                          "+f"(acc[mt][nt][2]), "+f"(acc[mt][nt][3])
                        : "r"(a[mt][0]), "r"(a[mt][1]), "r"(a[mt][2]), "r"(a[mt][3]),
                          "r"(b[nt][0]), "r"(b[nt][1]));
                }
        }
    };

    stage(0, 0);
    asm volatile("cp.async.commit_group;");
    for (int kt = 0; kt < KT; kt++) {
        int buf = kt & 1;
        if (kt + 1 < KT) {
            stage(kt + 1, buf ^ 1);
            asm volatile("cp.async.commit_group;");
            asm volatile("cp.async.wait_group 1;");
        } else {
            asm volatile("cp.async.wait_group 0;");
        }
        __syncthreads();
        compute(buf);
        __syncthreads();
    }

    const int r0 = bm + wm * 64 + (lane >> 2);
    const int cb = wn * 32 + 2 * (lane & 3);
#pragma unroll
    for (int mt = 0; mt < 4; mt++) {
#pragma unroll
        for (int nt = 0; nt < 4; nt++) {
            int row = r0 + mt * 16;
            int col = cb + nt * 8;
            float bx = bv[col], by = bv[col + 1];
            if (row < M) {
                float2 v = make_float2(acc[mt][nt][0] + bx, acc[mt][nt][1] + by);
                *(float2*)(C + (size_t)row * BN + col) = v;
            }
            if (row + 8 < M) {
                float2 v = make_float2(acc[mt][nt][2] + bx, acc[mt][nt][3] + by);
                *(float2*)(C + (size_t)(row + 8) * BN + col) = v;
            }
        }
    }
}

// ---------------- CSR construction (once per call) -----------------------------
__global__ void zero_counts(int* __restrict__ ci, int* __restrict__ cu) {
    int i = blockIdx.x * blockDim.x + threadIdx.x;
    if (i < NI) ci[i] = 0;
    if (i < NU) cu[i] = 0;
}

__global__ void build_hist(const int* __restrict__ es, const int* __restrict__ ed,
                           int* __restrict__ cu, int* __restrict__ ci, int nE) {
    int i = blockIdx.x * blockDim.x + threadIdx.x;
    if (i < nE) {
        atomicAdd(ci + ed[i], 1);
        atomicAdd(cu + es[i], 1);
    }
}

// single-block two-level exclusive scan; writes rowptr and cursor(=cnt reused)
__global__ __launch_bounds__(1024) void scan_rowptr(const int* __restrict__ cnt,
                                                    int* __restrict__ rp,
                                                    int* __restrict__ cur, int n) {
    __shared__ int ssum[1024];
    int tid = threadIdx.x;
    int chunk = (n + 1023) >> 10;
    int start = tid * chunk;
    int end = min(start + chunk, n);
    int s = 0;
    for (int i = start; i < end; i++) s += cnt[i];
    ssum[tid] = s;
    __syncthreads();
    for (int d = 1; d < 1024; d <<= 1) {
        int v = (tid >= d) ? ssum[tid - d] : 0;
        __syncthreads();
        ssum[tid] += v;
        __syncthreads();
    }
    int off = (tid > 0) ? ssum[tid - 1] : 0;
    for (int i = start; i < end; i++) {
        rp[i] = off;
        cur[i] = off;
        off += cnt[i];
    }
    if (tid == 1023) rp[n] = ssum[1023];
}

__global__ void fill_csr(const int* __restrict__ es, const int* __restrict__ ed,
                         int* __restrict__ cur_u, int* __restrict__ cur_i,
                         int* __restrict__ col_u, int* __restrict__ col_i, int nE) {
    int i = blockIdx.x * blockDim.x + threadIdx.x;
    if (i < nE) {
        int s = es[i], t = ed[i];
        col_i[atomicAdd(cur_i + t, 1)] = s;
        col_u[atomicAdd(cur_u + s, 1)] = t;
    }
}

// ---------------- fused GATv2 gather (both relations of one layer) -------------
// warp per destination node. warps [0, NI): rel0 (dst=item), [NI, NI+NU): rel1.
// lanes 0-15 = head 0 (dims 0..63), lanes 16-31 = head 1 (dims 64..127).
// Single pass per edge: logit -> pe = exp(logit); den += pe; acc += pe * xl[s].
__global__ __launch_bounds__(256) void gat_gather(
    const float* __restrict__ xlu, const float* __restrict__ xri,
    const float* __restrict__ att0, const float* __restrict__ bias0,
    float* __restrict__ outI,
    const float* __restrict__ xli, const float* __restrict__ xru,
    const float* __restrict__ att1, const float* __restrict__ bias1,
    float* __restrict__ outU,
    const int* __restrict__ rp_i, const int* __restrict__ col_i,
    const int* __restrict__ rp_u, const int* __restrict__ col_u)
{
    int w = (blockIdx.x * blockDim.x + threadIdx.x) >> 5;
    int lane = threadIdx.x & 31;

    const float* xl; const float* xr; const float* att; const float* bias;
    float* out; const int* rp; const int* col; int t;
    if (w < NI) {
        t = w; xl = xlu; xr = xri; att = att0; bias = bias0; out = outI;
        rp = rp_i; col = col_i;
    } else if (w < NI + NU) {
        t = w - NI; xl = xli; xr = xru; att = att1; bias = bias1; out = outU;
        rp = rp_u; col = col_u;
    } else return;

    int beg = rp[t], end = rp[t + 1];
    float4 b4 = *(const float4*)(bias + lane * 4);
    float* o = out + (size_t)t * H + lane * 4;

    if (beg == end) {
        *(float4*)o = b4;
        return;
    }

    float4 xr4 = *(const float4*)(xr + (size_t)t * H + lane * 4);
    float4 at4 = *(const float4*)(att + lane * 4);

    float a0 = 0.f, a1 = 0.f, a2 = 0.f, a3 = 0.f, den = 0.f;

    int e = beg;
    for (; e + 2 <= end; e += 2) {
        int s0 = col[e], s1 = col[e + 1];
        float4 xA = *(const float4*)(xl + (size_t)s0 * H + lane * 4);
        float4 xB = *(const float4*)(xl + (size_t)s1 * H + lane * 4);

        float eA0 = xA.x + xr4.x; eA0 = (eA0 > 0.f) ? eA0 : 0.2f * eA0;
        float eA1 = xA.y + xr4.y; eA1 = (eA1 > 0.f) ? eA1 : 0.2f * eA1;
        float eA2 = xA.z + xr4.z; eA2 = (eA2 > 0.f) ? eA2 : 0.2f * eA2;
        float eA3 = xA.w + xr4.w; eA3 = (eA3 > 0.f) ? eA3 : 0.2f * eA3;
        float pA = eA0 * at4.x + eA1 * at4.y + eA2 * at4.z + eA3 * at4.w;

        float eB0 = xB.x + xr4.x; eB0 = (eB0 > 0.f) ? eB0 : 0.2f * eB0;
        float eB1 = xB.y + xr4.y; eB1 = (eB1 > 0.f) ? eB1 : 0.2f * eB1;
        float eB2 = xB.z + xr4.z; eB2 = (eB2 > 0.f) ? eB2 : 0.2f * eB2;
        float eB3 = xB.w + xr4.w; eB3 = (eB3 > 0.f) ? eB3 : 0.2f * eB3;
        float pB = eB0 * at4.x + eB1 * at4.y + eB2 * at4.z + eB3 * at4.w;

#pragma unroll
        for (int off = 8; off > 0; off >>= 1) {
            pA += __shfl_xor_sync(0xffffffffu, pA, off);
            pB += __shfl_xor_sync(0xffffffffu, pB, off);
        }
        float peA = expf(pA);
        float peB = expf(pB);
        den += peA + peB;
        a0 += peA * xA.x + peB * xB.x;
        a1 += peA * xA.y + peB * xB.y;
        a2 += peA * xA.z + peB * xB.z;
        a3 += peA * xA.w + peB * xB.w;
    }
    if (e < end) {
        int s0 = col[e];
        float4 xA = *(const float4*)(xl + (size_t)s0 * H + lane * 4);
        float eA0 = xA.x + xr4.x; eA0 = (eA0 > 0.f) ? eA0 : 0.2f * eA0;
        float eA1 = xA.y + xr4.y; eA1 = (eA1 > 0.f) ? eA1 : 0.2f * eA1;
        float eA2 = xA.z + xr4.z; eA2 = (eA2 > 0.f) ? eA2 : 0.2f * eA2;
        float eA3 = xA.w + xr4.w; eA3 = (eA3 > 0.f) ? eA3 : 0.2f * eA3;
        float pA = eA0 * at4.x + eA1 * at4.y + eA2 * at4.z + eA3 * at4.w;
#pragma unroll
        for (int off = 8; off > 0; off >>= 1)
            pA += __shfl_xor_sync(0xffffffffu, pA, off);
        float peA = expf(pA);
        den += peA;
        a0 += peA * xA.x;
        a1 += peA * xA.y;
        a2 += peA * xA.z;
        a3 += peA * xA.w;
    }

    float inv = 1.f / (den + 1e-16f);
    float4 r;
    r.x = a0 * inv + b4.x;
    r.y = a1 * inv + b4.y;
    r.z = a2 * inv + b4.z;
    r.w = a3 * inv + b4.w;
    *(float4*)o = r;
}

extern "C" void kernel_launch(void* const* d_in, const int* in_sizes, int n_in,
                              void* d_out, int out_size)
{
    const float* x_user  = (const float*)d_in[0];
    const float* x_item  = (const float*)d_in[1];
    const float* Wp_user = (const float*)d_in[2];
    const float* bp_user = (const float*)d_in[3];
    const float* Wp_item = (const float*)d_in[4];
    const float* bp_item = (const float*)d_in[5];
    const float* Wl      = (const float*)d_in[6];
    const float* bl      = (const float*)d_in[7];
    const float* Wr      = (const float*)d_in[8];
    const float* br      = (const float*)d_in[9];
    const float* att     = (const float*)d_in[10];
    const float* bias    = (const float*)d_in[11];
    const int*   e_src   = (const int*)d_in[12];
    const int*   e_dst   = (const int*)d_in[13];
    const int    nE      = in_sizes[12];

    float* out = (float*)d_out;

    float *zu, *zi, *zu2, *zi2, *xlu, *xru, *xli, *xri;
    int *rp_i, *rp_u, *cnt_i, *cnt_u, *col_i, *col_u;
    cudaGetSymbolAddress((void**)&zu,  g_zu);
    cudaGetSymbolAddress((void**)&zi,  g_zi);
    cudaGetSymbolAddress((void**)&zu2, g_zu2);
    cudaGetSymbolAddress((void**)&zi2, g_zi2);
    cudaGetSymbolAddress((void**)&xlu, g_xlu);
    cudaGetSymbolAddress((void**)&xru, g_xru);
    cudaGetSymbolAddress((void**)&xli, g_xli);
    cudaGetSymbolAddress((void**)&xri, g_xri);
    cudaGetSymbolAddress((void**)&rp_i,  g_rp_i);
    cudaGetSymbolAddress((void**)&rp_u,  g_rp_u);
    cudaGetSymbolAddress((void**)&cnt_i, g_cnt_i);
    cudaGetSymbolAddress((void**)&cnt_u, g_cnt_u);
    cudaGetSymbolAddress((void**)&col_i, g_col_i);
    cudaGetSymbolAddress((void**)&col_u, g_col_u);

    cudaFuncSetAttribute(gemm_fused, cudaFuncAttributeMaxDynamicSharedMemorySize, SMEM_BYTES);

    cudaStream_t st = 0;
    const size_t HH = (size_t)H * H;
    const int UB = (NU + BM - 1) / BM;
    const int IB = (NI + BM - 1) / BM;

    // ---- CSR build (graph shared by both layers) ----
    zero_counts<<<(NU + 255) / 256, 256, 0, st>>>(cnt_i, cnt_u);
    build_hist<<<(nE + 255) / 256, 256, 0, st>>>(e_src, e_dst, cnt_u, cnt_i, nE);
    scan_rowptr<<<1, 1024, 0, st>>>(cnt_i, rp_i, cnt_i, NI);
    scan_rowptr<<<1, 1024, 0, st>>>(cnt_u, rp_u, cnt_u, NU);
    fill_csr<<<(nE + 255) / 256, 256, 0, st>>>(e_src, e_dst, cnt_u, cnt_i, col_u, col_i, nE);

    // ---- input projections ----
    {
        dim3 grid(1, UB + IB);
        gemm_fused<<<grid, 256, SMEM_BYTES, st>>>(
            x_user, NU, 64, x_item, NI, 128, UB,
            Wp_user, bp_user, zu,  Wp_user, bp_user, zu,
            Wp_item, bp_item, zi,  Wp_item, bp_item, zi, 0);
    }

    const int GBLK = ((NI + NU) * 32 + 255) / 256;

    for (int l = 0; l < 2; l++) {
        const float* inU = (l == 0) ? zu : zu2;
        const float* inI = (l == 0) ? zi : zi2;
        float* outU = (l == 0) ? zu2 : out;
        float* outI = (l == 0) ? zi2 : out + (size_t)NU * H;

        int r0 = l * 2 + 0;
        int r1 = l * 2 + 1;

        {
            dim3 grid(2, UB + IB);
            gemm_fused<<<grid, 256, SMEM_BYTES, st>>>(
                inU, NU, H, inI, NI, H, UB,
                Wl + r0 * HH, bl + (size_t)r0 * H, xlu,
                Wr + r1 * HH, br + (size_t)r1 * H, xru,
                Wr + r0 * HH, br + (size_t)r0 * H, xri,
                Wl + r1 * HH, bl + (size_t)r1 * H, xli,
                (l == 1) ? 1 : 0);
        }

        gat_gather<<<GBLK, 256, 0, st>>>(
            xlu, xri, att + (size_t)r0 * H, bias + (size_t)r0 * H, outI,
            xli, xru, att + (size_t)r1 * H, bias + (size_t)r1 * H, outU,
            rp_i, col_i, rp_u, col_u);
    }
}

// round 6
// speedup vs baseline: 3.4704x; 1.4542x over previous
#include <cuda_runtime.h>
#include <cstdint>

#define NU 100000
#define NI 20000
#define NE 250000
#define H  128
#define HEADS 2
#define D  64

// ---------------- scratch (static device arrays; no allocation) ----------------
__device__ float g_zu [NU * H];
__device__ float g_zi [NI * H];
__device__ float g_zu2[NU * H];
__device__ float g_zi2[NI * H];
__device__ float g_xlu[NU * H];
__device__ float g_xru[NU * H];
__device__ float g_xli[NI * H];
__device__ float g_xri[NI * H];

// CSR (built once per call; graph identical across layers)
__device__ int g_rp_i [NI + 1];
__device__ int g_rp_u [NU + 1];
__device__ int g_cnt_i[NI];
__device__ int g_cnt_u[NU];
__device__ int g_col_i[NE];
__device__ int g_col_u[NE];
__device__ int g_bsum_i[32];
__device__ int g_bsum_u[32];

// ---------------- tf32 tensor-core GEMM, cp.async 2-stage pipeline -------------
#define BM 128
#define BN 128
#define BK 32
#define AST 36
#define BST 136
#define SMEM_BYTES ((2*BM*AST + 2*BK*BST) * 4)

__device__ __forceinline__ uint32_t f2tf32(float x) {
    uint32_t u;
    asm("cvt.rna.tf32.f32 %0, %1;" : "=r"(u) : "f"(x));
    return u;
}

__device__ __forceinline__ void cp16(uint32_t dst, const float* src, bool pred) {
    asm volatile("cp.async.ca.shared.global [%0], [%1], 16, %2;"
                 :: "r"(dst), "l"(src), "r"(pred ? 16 : 0));
}

__global__ __launch_bounds__(256, 2) void gemm_fused(
    const float* __restrict__ Au, int Mu, int Ku,
    const float* __restrict__ Ai, int Mi, int Ki, int UB,
    const float* __restrict__ W00, const float* __restrict__ b00, float* __restrict__ C00,
    const float* __restrict__ W01, const float* __restrict__ b01, float* __restrict__ C01,
    const float* __restrict__ W10, const float* __restrict__ b10, float* __restrict__ C10,
    const float* __restrict__ W11, const float* __restrict__ b11, float* __restrict__ C11,
    int reluA)
{
    extern __shared__ float smbuf[];
    const int sec = (blockIdx.y >= (unsigned)UB) ? 1 : 0;
    const float* A = sec ? Ai : Au;
    const int M = sec ? Mi : Mu;
    const int K = sec ? Ki : Ku;
    const int bm = (sec ? (blockIdx.y - UB) : blockIdx.y) * BM;

    const float* W; const float* bv; float* C;
    if (!sec) { if (blockIdx.x == 0) { W=W00; bv=b00; C=C00; } else { W=W01; bv=b01; C=C01; } }
    else      { if (blockIdx.x == 0) { W=W10; bv=b10; C=C10; } else { W=W11; bv=b11; C=C11; } }

    const int tid  = threadIdx.x;
    const int lane = tid & 31;
    const int warp = tid >> 5;
    const int wm   = warp >> 2;
    const int wn   = warp & 3;

    float* As = smbuf;
    float* Bs = smbuf + 2 * BM * AST;

    const int arow = tid >> 3;
    const int acol = (tid & 7) * 4;
    const int brow = tid >> 5;
    const int bcol = (tid & 31) * 4;

    float acc[4][4][4];
#pragma unroll
    for (int mt = 0; mt < 4; mt++)
#pragma unroll
        for (int nt = 0; nt < 4; nt++)
#pragma unroll
            for (int c = 0; c < 4; c++) acc[mt][nt][c] = 0.f;

    const int KT = K / BK;

    auto stage = [&](int kt, int buf) {
#pragma unroll
        for (int i = 0; i < 4; i++) {
            int row = arow + 32 * i;
            bool p = (bm + row) < M;
            int r = p ? (bm + row) : (M - 1);
            uint32_t d = (uint32_t)__cvta_generic_to_shared(As + buf * BM * AST + row * AST + acol);
            cp16(d, A + (size_t)r * K + kt * BK + acol, p);
        }
#pragma unroll
        for (int i = 0; i < 4; i++) {
            int kr = brow + 8 * i;
            uint32_t d = (uint32_t)__cvta_generic_to_shared(Bs + buf * BK * BST + kr * BST + bcol);
            cp16(d, W + (size_t)(kt * BK + kr) * BN + bcol, true);
        }
    };

    auto compute = [&](int buf) {
        const float* Asb = As + buf * BM * AST;
        const float* Bsb = Bs + buf * BK * BST;
#pragma unroll
        for (int kk = 0; kk < 4; kk++) {
            uint32_t a[4][4];
            {
                int row  = wm * 64 + (lane & 15);
                int koff = kk * 8 + ((lane >> 4) << 2);
#pragma unroll
                for (int mt = 0; mt < 4; mt++) {
                    uint32_t sa = (uint32_t)__cvta_generic_to_shared(
                        Asb + (row + mt * 16) * AST + koff);
                    asm volatile(
                        "ldmatrix.sync.aligned.m8n8.x4.shared.b16 {%0,%1,%2,%3}, [%4];"
                        : "=r"(a[mt][0]), "=r"(a[mt][1]), "=r"(a[mt][2]), "=r"(a[mt][3])
                        : "r"(sa));
                }
            }
            if (reluA) {
#pragma unroll
                for (int mt = 0; mt < 4; mt++)
#pragma unroll
                    for (int i = 0; i < 4; i++)
                        a[mt][i] = __float_as_uint(fmaxf(__uint_as_float(a[mt][i]), 0.f));
            }
#pragma unroll
            for (int mt = 0; mt < 4; mt++)
#pragma unroll
                for (int i = 0; i < 4; i++)
                    a[mt][i] = f2tf32(__uint_as_float(a[mt][i]));

            uint32_t b[4][2];
            {
                int kb = kk * 8 + (lane & 3);
                int nb = wn * 32 + (lane >> 2);
#pragma unroll
                for (int nt = 0; nt < 4; nt++) {
                    b[nt][0] = f2tf32(Bsb[kb * BST + nb + nt * 8]);
                    b[nt][1] = f2tf32(Bsb[(kb + 4) * BST + nb + nt * 8]);
                }
            }
#pragma unroll
            for (int mt = 0; mt < 4; mt++)
#pragma unroll
                for (int nt = 0; nt < 4; nt++) {
                    asm volatile(
                        "mma.sync.aligned.m16n8k8.row.col.f32.tf32.tf32.f32 "
                        "{%0,%1,%2,%3}, {%4,%5,%6,%7}, {%8,%9}, {%0,%1,%2,%3};"
                        : "+f"(acc[mt][nt][0]), "+f"(acc[mt][nt][1]),
                          "+f"(acc[mt][nt][2]), "+f"(acc[mt][nt][3])
                        : "r"(a[mt][0]), "r"(a[mt][1]), "r"(a[mt][2]), "r"(a[mt][3]),
                          "r"(b[nt][0]), "r"(b[nt][1]));
                }
        }
    };

    stage(0, 0);
    asm volatile("cp.async.commit_group;");
    for (int kt = 0; kt < KT; kt++) {
        int buf = kt & 1;
        if (kt + 1 < KT) {
            stage(kt + 1, buf ^ 1);
            asm volatile("cp.async.commit_group;");
            asm volatile("cp.async.wait_group 1;");
        } else {
            asm volatile("cp.async.wait_group 0;");
        }
        __syncthreads();
        compute(buf);
        __syncthreads();
    }

    const int r0 = bm + wm * 64 + (lane >> 2);
    const int cb = wn * 32 + 2 * (lane & 3);
#pragma unroll
    for (int mt = 0; mt < 4; mt++) {
#pragma unroll
        for (int nt = 0; nt < 4; nt++) {
            int row = r0 + mt * 16;
            int col = cb + nt * 8;
            float bx = bv[col], by = bv[col + 1];
            if (row < M) {
                float2 v = make_float2(acc[mt][nt][0] + bx, acc[mt][nt][1] + by);
                *(float2*)(C + (size_t)row * BN + col) = v;
            }
            if (row + 8 < M) {
                float2 v = make_float2(acc[mt][nt][2] + bx, acc[mt][nt][3] + by);
                *(float2*)(C + (size_t)(row + 8) * BN + col) = v;
            }
        }
    }
}

// ---------------- CSR construction (once per call) -----------------------------
__global__ void zero_counts(int* __restrict__ ci, int* __restrict__ cu) {
    int i = blockIdx.x * blockDim.x + threadIdx.x;
    if (i < NI) ci[i] = 0;
    if (i < NU) cu[i] = 0;
}

__global__ void build_hist(const int* __restrict__ es, const int* __restrict__ ed,
                           int* __restrict__ cu, int* __restrict__ ci, int nE) {
    int i = blockIdx.x * blockDim.x + threadIdx.x;
    if (i < nE) {
        atomicAdd(ci + ed[i], 1);
        atomicAdd(cu + es[i], 1);
    }
}

// ---- 3-phase device-wide exclusive scan (4096 elems / block) ----
__global__ __launch_bounds__(1024) void scan_p1(const int* __restrict__ cnt,
                                                int* __restrict__ bsums, int n) {
    __shared__ int sh[1024];
    int base = blockIdx.x * 4096;
    int t = threadIdx.x;
    int s = 0;
#pragma unroll
    for (int j = 0; j < 4; j++) {
        int i = base + t * 4 + j;
        if (i < n) s += cnt[i];
    }
    sh[t] = s;
    __syncthreads();
    for (int d = 512; d > 0; d >>= 1) {
        if (t < d) sh[t] += sh[t + d];
        __syncthreads();
    }
    if (t == 0) bsums[blockIdx.x] = sh[0];
}

// one warp: exclusive scan of <=32 block sums; also writes rp[n] = total
__global__ void scan_p2(int* __restrict__ bsums, int nb, int* __restrict__ rp, int n) {
    int t = threadIdx.x;
    int own = (t < nb) ? bsums[t] : 0;
    int v = own;
#pragma unroll
    for (int d = 1; d < 32; d <<= 1) {
        int u = __shfl_up_sync(0xffffffffu, v, d);
        if (t >= d) v += u;
    }
    if (t < nb) bsums[t] = v - own;       // exclusive
    if (t == nb - 1) rp[n] = v;           // grand total
}

__global__ __launch_bounds__(1024) void scan_p3(const int* __restrict__ cnt,
                                                const int* __restrict__ bsums,
                                                int* __restrict__ rp,
                                                int* __restrict__ cur, int n) {
    __shared__ int sh[1024];
    int base = blockIdx.x * 4096;
    int t = threadIdx.x;
    int c[4];
    int s = 0;
#pragma unroll
    for (int j = 0; j < 4; j++) {
        int i = base + t * 4 + j;
        c[j] = (i < n) ? cnt[i] : 0;
        s += c[j];
    }
    sh[t] = s;
    __syncthreads();
    for (int d = 1; d < 1024; d <<= 1) {
        int v = (t >= d) ? sh[t - d] : 0;
        __syncthreads();
        sh[t] += v;
        __syncthreads();
    }
    int off = bsums[blockIdx.x] + ((t > 0) ? sh[t - 1] : 0);
#pragma unroll
    for (int j = 0; j < 4; j++) {
        int i = base + t * 4 + j;
        if (i < n) {
            rp[i] = off;
            cur[i] = off;
            off += c[j];
        }
    }
}

__global__ void fill_csr(const int* __restrict__ es, const int* __restrict__ ed,
                         int* __restrict__ cur_u, int* __restrict__ cur_i,
                         int* __restrict__ col_u, int* __restrict__ col_i, int nE) {
    int i = blockIdx.x * blockDim.x + threadIdx.x;
    if (i < nE) {
        int s = es[i], t = ed[i];
        col_i[atomicAdd(cur_i + t, 1)] = s;
        col_u[atomicAdd(cur_u + s, 1)] = t;
    }
}

// ---------------- fused GATv2 gather (both relations of one layer) -------------
__global__ __launch_bounds__(256) void gat_gather(
    const float* __restrict__ xlu, const float* __restrict__ xri,
    const float* __restrict__ att0, const float* __restrict__ bias0,
    float* __restrict__ outI,
    const float* __restrict__ xli, const float* __restrict__ xru,
    const float* __restrict__ att1, const float* __restrict__ bias1,
    float* __restrict__ outU,
    const int* __restrict__ rp_i, const int* __restrict__ col_i,
    const int* __restrict__ rp_u, const int* __restrict__ col_u)
{
    int w = (blockIdx.x * blockDim.x + threadIdx.x) >> 5;
    int lane = threadIdx.x & 31;

    const float* xl; const float* xr; const float* att; const float* bias;
    float* out; const int* rp; const int* col; int t;
    if (w < NI) {
        t = w; xl = xlu; xr = xri; att = att0; bias = bias0; out = outI;
        rp = rp_i; col = col_i;
    } else if (w < NI + NU) {
        t = w - NI; xl = xli; xr = xru; att = att1; bias = bias1; out = outU;
        rp = rp_u; col = col_u;
    } else return;

    int beg = rp[t], end = rp[t + 1];
    float4 b4 = *(const float4*)(bias + lane * 4);
    float* o = out + (size_t)t * H + lane * 4;

    if (beg == end) {
        *(float4*)o = b4;
        return;
    }

    float4 xr4 = *(const float4*)(xr + (size_t)t * H + lane * 4);
    float4 at4 = *(const float4*)(att + lane * 4);

    float a0 = 0.f, a1 = 0.f, a2 = 0.f, a3 = 0.f, den = 0.f;

    int e = beg;
    for (; e + 2 <= end; e += 2) {
        int s0 = col[e], s1 = col[e + 1];
        float4 xA = *(const float4*)(xl + (size_t)s0 * H + lane * 4);
        float4 xB = *(const float4*)(xl + (size_t)s1 * H + lane * 4);

        float eA0 = xA.x + xr4.x; eA0 = (eA0 > 0.f) ? eA0 : 0.2f * eA0;
        float eA1 = xA.y + xr4.y; eA1 = (eA1 > 0.f) ? eA1 : 0.2f * eA1;
        float eA2 = xA.z + xr4.z; eA2 = (eA2 > 0.f) ? eA2 : 0.2f * eA2;
        float eA3 = xA.w + xr4.w; eA3 = (eA3 > 0.f) ? eA3 : 0.2f * eA3;
        float pA = eA0 * at4.x + eA1 * at4.y + eA2 * at4.z + eA3 * at4.w;

        float eB0 = xB.x + xr4.x; eB0 = (eB0 > 0.f) ? eB0 : 0.2f * eB0;
        float eB1 = xB.y + xr4.y; eB1 = (eB1 > 0.f) ? eB1 : 0.2f * eB1;
        float eB2 = xB.z + xr4.z; eB2 = (eB2 > 0.f) ? eB2 : 0.2f * eB2;
        float eB3 = xB.w + xr4.w; eB3 = (eB3 > 0.f) ? eB3 : 0.2f * eB3;
        float pB = eB0 * at4.x + eB1 * at4.y + eB2 * at4.z + eB3 * at4.w;

#pragma unroll
        for (int off = 8; off > 0; off >>= 1) {
            pA += __shfl_xor_sync(0xffffffffu, pA, off);
            pB += __shfl_xor_sync(0xffffffffu, pB, off);
        }
        float peA = expf(pA);
        float peB = expf(pB);
        den += peA + peB;
        a0 += peA * xA.x + peB * xB.x;
        a1 += peA * xA.y + peB * xB.y;
        a2 += peA * xA.z + peB * xB.z;
        a3 += peA * xA.w + peB * xB.w;
    }
    if (e < end) {
        int s0 = col[e];
        float4 xA = *(const float4*)(xl + (size_t)s0 * H + lane * 4);
        float eA0 = xA.x + xr4.x; eA0 = (eA0 > 0.f) ? eA0 : 0.2f * eA0;
        float eA1 = xA.y + xr4.y; eA1 = (eA1 > 0.f) ? eA1 : 0.2f * eA1;
        float eA2 = xA.z + xr4.z; eA2 = (eA2 > 0.f) ? eA2 : 0.2f * eA2;
        float eA3 = xA.w + xr4.w; eA3 = (eA3 > 0.f) ? eA3 : 0.2f * eA3;
        float pA = eA0 * at4.x + eA1 * at4.y + eA2 * at4.z + eA3 * at4.w;
#pragma unroll
        for (int off = 8; off > 0; off >>= 1)
            pA += __shfl_xor_sync(0xffffffffu, pA, off);
        float peA = expf(pA);
        den += peA;
        a0 += peA * xA.x;
        a1 += peA * xA.y;
        a2 += peA * xA.z;
        a3 += peA * xA.w;
    }

    float inv = 1.f / (den + 1e-16f);
    float4 r;
    r.x = a0 * inv + b4.x;
    r.y = a1 * inv + b4.y;
    r.z = a2 * inv + b4.z;
    r.w = a3 * inv + b4.w;
    *(float4*)o = r;
}

extern "C" void kernel_launch(void* const* d_in, const int* in_sizes, int n_in,
                              void* d_out, int out_size)
{
    const float* x_user  = (const float*)d_in[0];
    const float* x_item  = (const float*)d_in[1];
    const float* Wp_user = (const float*)d_in[2];
    const float* bp_user = (const float*)d_in[3];
    const float* Wp_item = (const float*)d_in[4];
    const float* bp_item = (const float*)d_in[5];
    const float* Wl      = (const float*)d_in[6];
    const float* bl      = (const float*)d_in[7];
    const float* Wr      = (const float*)d_in[8];
    const float* br      = (const float*)d_in[9];
    const float* att     = (const float*)d_in[10];
    const float* bias    = (const float*)d_in[11];
    const int*   e_src   = (const int*)d_in[12];
    const int*   e_dst   = (const int*)d_in[13];
    const int    nE      = in_sizes[12];

    float* out = (float*)d_out;

    float *zu, *zi, *zu2, *zi2, *xlu, *xru, *xli, *xri;
    int *rp_i, *rp_u, *cnt_i, *cnt_u, *col_i, *col_u, *bs_i, *bs_u;
    cudaGetSymbolAddress((void**)&zu,  g_zu);
    cudaGetSymbolAddress((void**)&zi,  g_zi);
    cudaGetSymbolAddress((void**)&zu2, g_zu2);
    cudaGetSymbolAddress((void**)&zi2, g_zi2);
    cudaGetSymbolAddress((void**)&xlu, g_xlu);
    cudaGetSymbolAddress((void**)&xru, g_xru);
    cudaGetSymbolAddress((void**)&xli, g_xli);
    cudaGetSymbolAddress((void**)&xri, g_xri);
    cudaGetSymbolAddress((void**)&rp_i,  g_rp_i);
    cudaGetSymbolAddress((void**)&rp_u,  g_rp_u);
    cudaGetSymbolAddress((void**)&cnt_i, g_cnt_i);
    cudaGetSymbolAddress((void**)&cnt_u, g_cnt_u);
    cudaGetSymbolAddress((void**)&col_i, g_col_i);
    cudaGetSymbolAddress((void**)&col_u, g_col_u);
    cudaGetSymbolAddress((void**)&bs_i,  g_bsum_i);
    cudaGetSymbolAddress((void**)&bs_u,  g_bsum_u);

    cudaFuncSetAttribute(gemm_fused, cudaFuncAttributeMaxDynamicSharedMemorySize, SMEM_BYTES);

    cudaStream_t st = 0;
    const size_t HH = (size_t)H * H;
    const int UB = (NU + BM - 1) / BM;
    const int IB = (NI + BM - 1) / BM;
    const int NB_I = (NI + 4095) / 4096;   // 5
    const int NB_U = (NU + 4095) / 4096;   // 25

    // ---- CSR build (graph shared by both layers) ----
    zero_counts<<<(NU + 255) / 256, 256, 0, st>>>(cnt_i, cnt_u);
    build_hist<<<(nE + 255) / 256, 256, 0, st>>>(e_src, e_dst, cnt_u, cnt_i, nE);
    scan_p1<<<NB_I, 1024, 0, st>>>(cnt_i, bs_i, NI);
    scan_p1<<<NB_U, 1024, 0, st>>>(cnt_u, bs_u, NU);
    scan_p2<<<1, 32, 0, st>>>(bs_i, NB_I, rp_i, NI);
    scan_p2<<<1, 32, 0, st>>>(bs_u, NB_U, rp_u, NU);
    scan_p3<<<NB_I, 1024, 0, st>>>(cnt_i, bs_i, rp_i, cnt_i, NI);
    scan_p3<<<NB_U, 1024, 0, st>>>(cnt_u, bs_u, rp_u, cnt_u, NU);
    fill_csr<<<(nE + 255) / 256, 256, 0, st>>>(e_src, e_dst, cnt_u, cnt_i, col_u, col_i, nE);

    // ---- input projections ----
    {
        dim3 grid(1, UB + IB);
        gemm_fused<<<grid, 256, SMEM_BYTES, st>>>(
            x_user, NU, 64, x_item, NI, 128, UB,
            Wp_user, bp_user, zu,  Wp_user, bp_user, zu,
            Wp_item, bp_item, zi,  Wp_item, bp_item, zi, 0);
    }

    const int GBLK = ((NI + NU) * 32 + 255) / 256;

    for (int l = 0; l < 2; l++) {
        const float* inU = (l == 0) ? zu : zu2;
        const float* inI = (l == 0) ? zi : zi2;
        float* outU = (l == 0) ? zu2 : out;
        float* outI = (l == 0) ? zi2 : out + (size_t)NU * H;

        int r0 = l * 2 + 0;
        int r1 = l * 2 + 1;

        {
            dim3 grid(2, UB + IB);
            gemm_fused<<<grid, 256, SMEM_BYTES, st>>>(
                inU, NU, H, inI, NI, H, UB,
                Wl + r0 * HH, bl + (size_t)r0 * H, xlu,
                Wr + r1 * HH, br + (size_t)r1 * H, xru,
                Wr + r0 * HH, br + (size_t)r0 * H, xri,
                Wl + r1 * HH, bl + (size_t)r1 * H, xli,
                (l == 1) ? 1 : 0);
        }

        gat_gather<<<GBLK, 256, 0, st>>>(
            xlu, xri, att + (size_t)r0 * H, bias + (size_t)r0 * H, outI,
            xli, xru, att + (size_t)r1 * H, bias + (size_t)r1 * H, outU,
            rp_i, col_i, rp_u, col_u);
    }
}

// round 7
// speedup vs baseline: 3.6451x; 1.0503x over previous
#include <cuda_runtime.h>
#include <cstdint>

#define NU 100000
#define NI 20000
#define NE 250000
#define H  128
#define HEADS 2
#define D  64

// ---------------- scratch (static device arrays; no allocation) ----------------
__device__ float g_zu [NU * H];
__device__ float g_zi [NI * H];
__device__ float g_zu2[NU * H];
__device__ float g_zi2[NI * H];
__device__ float g_xlu[NU * H];
__device__ float g_xru[NU * H];
__device__ float g_xli[NI * H];
__device__ float g_xri[NI * H];
__device__ float g_wtf[155648];     // tf32-rounded weights

// CSR (built once per call; graph identical across layers)
__device__ int g_rp_i [NI + 1];
__device__ int g_rp_u [NU + 1];
__device__ int g_cnt_i[NI];
__device__ int g_cnt_u[NU];
__device__ int g_col_i[NE];
__device__ int g_col_u[NE];
__device__ int g_bsum_i[32];
__device__ int g_bsum_u[32];

// ---------------- tf32 helpers -------------------------------------------------
__device__ __forceinline__ uint32_t f2tf32(float x) {
    uint32_t u;
    asm("cvt.rna.tf32.f32 %0, %1;" : "=r"(u) : "f"(x));
    return u;
}
__device__ __forceinline__ float rndtf32(float x) {
    return __uint_as_float(f2tf32(x));
}

// pre-round all weight matrices once per call
// layout: [Wp_user 8192][Wp_item 16384][Wl 4x16384][Wr 4x16384]
#define WO_PU 0
#define WO_PI 8192
#define WO_WL 24576
#define WO_WR 90112
#define W_TOT 155648
__global__ void round_w(const float* __restrict__ pu, const float* __restrict__ pi,
                        const float* __restrict__ wl, const float* __restrict__ wr,
                        float* __restrict__ o) {
    int i = blockIdx.x * blockDim.x + threadIdx.x;
    float v;
    if (i < WO_PI) v = pu[i];
    else if (i < WO_WL) v = pi[i - WO_PI];
    else if (i < WO_WR) v = wl[i - WO_WL];
    else if (i < W_TOT) v = wr[i - WO_WR];
    else return;
    o[i] = rndtf32(v);
}

// ---------------- tf32 tensor-core GEMM, cp.async 2-stage pipeline -------------
#define BM 128
#define BN 128
#define BK 32
#define AST 36
#define BST 136
#define SMEM_BYTES ((2*BM*AST + 2*BK*BST) * 4)

__device__ __forceinline__ void cp16(uint32_t dst, const float* src, bool pred) {
    asm volatile("cp.async.ca.shared.global [%0], [%1], 16, %2;"
                 :: "r"(dst), "l"(src), "r"(pred ? 16 : 0));
}

__global__ __launch_bounds__(256, 2) void gemm_fused(
    const float* __restrict__ Au, int Mu, int Ku,
    const float* __restrict__ Ai, int Mi, int Ki, int UB,
    const float* __restrict__ W00, const float* __restrict__ b00, float* __restrict__ C00,
    const float* __restrict__ W01, const float* __restrict__ b01, float* __restrict__ C01,
    const float* __restrict__ W10, const float* __restrict__ b10, float* __restrict__ C10,
    const float* __restrict__ W11, const float* __restrict__ b11, float* __restrict__ C11,
    int reluA, int cvtA, int roundC)
{
    extern __shared__ float smbuf[];
    const int sec = (blockIdx.y >= (unsigned)UB) ? 1 : 0;
    const float* A = sec ? Ai : Au;
    const int M = sec ? Mi : Mu;
    const int K = sec ? Ki : Ku;
    const int bm = (sec ? (blockIdx.y - UB) : blockIdx.y) * BM;

    const float* W; const float* bv; float* C;
    if (!sec) { if (blockIdx.x == 0) { W=W00; bv=b00; C=C00; } else { W=W01; bv=b01; C=C01; } }
    else      { if (blockIdx.x == 0) { W=W10; bv=b10; C=C10; } else { W=W11; bv=b11; C=C11; } }

    const int tid  = threadIdx.x;
    const int lane = tid & 31;
    const int warp = tid >> 5;
    const int wm   = warp >> 2;
    const int wn   = warp & 3;

    float* As = smbuf;
    float* Bs = smbuf + 2 * BM * AST;

    const int arow = tid >> 3;
    const int acol = (tid & 7) * 4;
    const int brow = tid >> 5;
    const int bcol = (tid & 31) * 4;

    float acc[4][4][4];
#pragma unroll
    for (int mt = 0; mt < 4; mt++)
#pragma unroll
        for (int nt = 0; nt < 4; nt++)
#pragma unroll
            for (int c = 0; c < 4; c++) acc[mt][nt][c] = 0.f;

    const int KT = K / BK;

    auto stage = [&](int kt, int buf) {
#pragma unroll
        for (int i = 0; i < 4; i++) {
            int row = arow + 32 * i;
            bool p = (bm + row) < M;
            int r = p ? (bm + row) : (M - 1);
            uint32_t d = (uint32_t)__cvta_generic_to_shared(As + buf * BM * AST + row * AST + acol);
            cp16(d, A + (size_t)r * K + kt * BK + acol, p);
        }
#pragma unroll
        for (int i = 0; i < 4; i++) {
            int kr = brow + 8 * i;
            uint32_t d = (uint32_t)__cvta_generic_to_shared(Bs + buf * BK * BST + kr * BST + bcol);
            cp16(d, W + (size_t)(kt * BK + kr) * BN + bcol, true);
        }
    };

    auto compute = [&](int buf) {
        const float* Asb = As + buf * BM * AST;
        const float* Bsb = Bs + buf * BK * BST;
#pragma unroll
        for (int kk = 0; kk < 4; kk++) {
            uint32_t a[4][4];
            {
                int row  = wm * 64 + (lane & 15);
                int koff = kk * 8 + ((lane >> 4) << 2);
#pragma unroll
                for (int mt = 0; mt < 4; mt++) {
                    uint32_t sa = (uint32_t)__cvta_generic_to_shared(
                        Asb + (row + mt * 16) * AST + koff);
                    asm volatile(
                        "ldmatrix.sync.aligned.m8n8.x4.shared.b16 {%0,%1,%2,%3}, [%4];"
                        : "=r"(a[mt][0]), "=r"(a[mt][1]), "=r"(a[mt][2]), "=r"(a[mt][3])
                        : "r"(sa));
                }
            }
            if (reluA) {
#pragma unroll
                for (int mt = 0; mt < 4; mt++)
#pragma unroll
                    for (int i = 0; i < 4; i++)
                        a[mt][i] = __float_as_uint(fmaxf(__uint_as_float(a[mt][i]), 0.f));
            }
            if (cvtA) {
#pragma unroll
                for (int mt = 0; mt < 4; mt++)
#pragma unroll
                    for (int i = 0; i < 4; i++)
                        a[mt][i] = f2tf32(__uint_as_float(a[mt][i]));
            }

            uint32_t b[4][2];
            {
                int kb = kk * 8 + (lane & 3);
                int nb = wn * 32 + (lane >> 2);
#pragma unroll
                for (int nt = 0; nt < 4; nt++) {
                    b[nt][0] = __float_as_uint(Bsb[kb * BST + nb + nt * 8]);
                    b[nt][1] = __float_as_uint(Bsb[(kb + 4) * BST + nb + nt * 8]);
                }
            }
#pragma unroll
            for (int mt = 0; mt < 4; mt++)
#pragma unroll
                for (int nt = 0; nt < 4; nt++) {
                    asm volatile(
                        "mma.sync.aligned.m16n8k8.row.col.f32.tf32.tf32.f32 "
                        "{%0,%1,%2,%3}, {%4,%5,%6,%7}, {%8,%9}, {%0,%1,%2,%3};"
                        : "+f"(acc[mt][nt][0]), "+f"(acc[mt][nt][1]),
                          "+f"(acc[mt][nt][2]), "+f"(acc[mt][nt][3])
                        : "r"(a[mt][0]), "r"(a[mt][1]), "r"(a[mt][2]), "r"(a[mt][3]),
                          "r"(b[nt][0]), "r"(b[nt][1]));
                }
        }
    };

    stage(0, 0);
    asm volatile("cp.async.commit_group;");
    for (int kt = 0; kt < KT; kt++) {
        int buf = kt & 1;
        if (kt + 1 < KT) {
            stage(kt + 1, buf ^ 1);
            asm volatile("cp.async.commit_group;");
            asm volatile("cp.async.wait_group 1;");
        } else {
            asm volatile("cp.async.wait_group 0;");
        }
        __syncthreads();
        compute(buf);
        __syncthreads();
    }

    const int r0 = bm + wm * 64 + (lane >> 2);
    const int cb = wn * 32 + 2 * (lane & 3);
#pragma unroll
    for (int mt = 0; mt < 4; mt++) {
#pragma unroll
        for (int nt = 0; nt < 4; nt++) {
            int row = r0 + mt * 16;
            int col = cb + nt * 8;
            float bx = bv[col], by = bv[col + 1];
            if (row < M) {
                float2 v = make_float2(acc[mt][nt][0] + bx, acc[mt][nt][1] + by);
                if (roundC) { v.x = rndtf32(v.x); v.y = rndtf32(v.y); }
                *(float2*)(C + (size_t)row * BN + col) = v;
            }
            if (row + 8 < M) {
                float2 v = make_float2(acc[mt][nt][2] + bx, acc[mt][nt][3] + by);
                if (roundC) { v.x = rndtf32(v.x); v.y = rndtf32(v.y); }
                *(float2*)(C + (size_t)(row + 8) * BN + col) = v;
            }
        }
    }
}

// ---------------- CSR construction (once per call) -----------------------------
__global__ void zero_counts(int* __restrict__ ci, int* __restrict__ cu) {
    int i = blockIdx.x * blockDim.x + threadIdx.x;
    if (i < NI) ci[i] = 0;
    if (i < NU) cu[i] = 0;
}

__global__ void build_hist(const int* __restrict__ es, const int* __restrict__ ed,
                           int* __restrict__ cu, int* __restrict__ ci, int nE) {
    int i = blockIdx.x * blockDim.x + threadIdx.x;
    if (i < nE) {
        atomicAdd(ci + ed[i], 1);
        atomicAdd(cu + es[i], 1);
    }
}

// ---- dual 3-phase device-wide exclusive scan (4096 elems / block) ----
__global__ __launch_bounds__(1024) void scan_p1_both(
    const int* __restrict__ ci, int* __restrict__ bi, int nbi, int ni,
    const int* __restrict__ cu, int* __restrict__ bu, int nu)
{
    __shared__ int sh[1024];
    const int* cnt; int* bsums; int n; int blk;
    if ((int)blockIdx.x < nbi) { cnt = ci; bsums = bi; n = ni; blk = blockIdx.x; }
    else { cnt = cu; bsums = bu; n = nu; blk = blockIdx.x - nbi; }
    int base = blk * 4096;
    int t = threadIdx.x;
    int s = 0;
#pragma unroll
    for (int j = 0; j < 4; j++) {
        int i = base + t * 4 + j;
        if (i < n) s += cnt[i];
    }
    sh[t] = s;
    __syncthreads();
    for (int d = 512; d > 0; d >>= 1) {
        if (t < d) sh[t] += sh[t + d];
        __syncthreads();
    }
    if (t == 0) bsums[blk] = sh[0];
}

__global__ void scan_p2_both(int* __restrict__ bi, int nbi, int* __restrict__ rpi, int ni,
                             int* __restrict__ bu, int nbu, int* __restrict__ rpu, int nu) {
    int w = threadIdx.x >> 5;
    int t = threadIdx.x & 31;
    int* bs = w ? bu : bi;
    int nb = w ? nbu : nbi;
    int* rp = w ? rpu : rpi;
    int n  = w ? nu : ni;
    int own = (t < nb) ? bs[t] : 0;
    int v = own;
#pragma unroll
    for (int d = 1; d < 32; d <<= 1) {
        int u = __shfl_up_sync(0xffffffffu, v, d);
        if (t >= d) v += u;
    }
    if (t < nb) bs[t] = v - own;
    if (t == nb - 1) rp[n] = v;
}

__global__ __launch_bounds__(1024) void scan_p3_both(
    const int* __restrict__ ci, const int* __restrict__ bi, int nbi,
    int* __restrict__ rpi, int* __restrict__ curi, int ni,
    const int* __restrict__ cu, const int* __restrict__ bu,
    int* __restrict__ rpu, int* __restrict__ curu, int nu)
{
    __shared__ int sh[1024];
    const int* cnt; const int* bsums; int* rp; int* cur; int n; int blk;
    if ((int)blockIdx.x < nbi) { cnt = ci; bsums = bi; rp = rpi; cur = curi; n = ni; blk = blockIdx.x; }
    else { cnt = cu; bsums = bu; rp = rpu; cur = curu; n = nu; blk = blockIdx.x - nbi; }
    int base = blk * 4096;
    int t = threadIdx.x;
    int c[4];
    int s = 0;
#pragma unroll
    for (int j = 0; j < 4; j++) {
        int i = base + t * 4 + j;
        c[j] = (i < n) ? cnt[i] : 0;
        s += c[j];
    }
    sh[t] = s;
    __syncthreads();
    for (int d = 1; d < 1024; d <<= 1) {
        int v = (t >= d) ? sh[t - d] : 0;
        __syncthreads();
        sh[t] += v;
        __syncthreads();
    }
    int off = bsums[blk] + ((t > 0) ? sh[t - 1] : 0);
#pragma unroll
    for (int j = 0; j < 4; j++) {
        int i = base + t * 4 + j;
        if (i < n) {
            rp[i] = off;
            cur[i] = off;
            off += c[j];
        }
    }
}

__global__ void fill_csr(const int* __restrict__ es, const int* __restrict__ ed,
                         int* __restrict__ cur_u, int* __restrict__ cur_i,
                         int* __restrict__ col_u, int* __restrict__ col_i, int nE) {
    int i = blockIdx.x * blockDim.x + threadIdx.x;
    if (i < nE) {
        int s = es[i], t = ed[i];
        col_i[atomicAdd(cur_i + t, 1)] = s;
        col_u[atomicAdd(cur_u + s, 1)] = t;
    }
}

// ---------------- fused GATv2 gather (both relations of one layer) -------------
__global__ __launch_bounds__(256) void gat_gather(
    const float* __restrict__ xlu, const float* __restrict__ xri,
    const float* __restrict__ att0, const float* __restrict__ bias0,
    float* __restrict__ outI,
    const float* __restrict__ xli, const float* __restrict__ xru,
    const float* __restrict__ att1, const float* __restrict__ bias1,
    float* __restrict__ outU,
    const int* __restrict__ rp_i, const int* __restrict__ col_i,
    const int* __restrict__ rp_u, const int* __restrict__ col_u,
    int roundOut)
{
    int w = (blockIdx.x * blockDim.x + threadIdx.x) >> 5;
    int lane = threadIdx.x & 31;

    const float* xl; const float* xr; const float* att; const float* bias;
    float* out; const int* rp; const int* col; int t;
    if (w < NI) {
        t = w; xl = xlu; xr = xri; att = att0; bias = bias0; out = outI;
        rp = rp_i; col = col_i;
    } else if (w < NI + NU) {
        t = w - NI; xl = xli; xr = xru; att = att1; bias = bias1; out = outU;
        rp = rp_u; col = col_u;
    } else return;

    int beg = rp[t], end = rp[t + 1];
    float4 b4 = *(const float4*)(bias + lane * 4);
    float* o = out + (size_t)t * H + lane * 4;

    if (beg == end) {
        if (roundOut) {
            b4.x = rndtf32(b4.x); b4.y = rndtf32(b4.y);
            b4.z = rndtf32(b4.z); b4.w = rndtf32(b4.w);
        }
        *(float4*)o = b4;
        return;
    }

    float4 xr4 = *(const float4*)(xr + (size_t)t * H + lane * 4);
    float4 at4 = *(const float4*)(att + lane * 4);

    float a0 = 0.f, a1 = 0.f, a2 = 0.f, a3 = 0.f, den = 0.f;

    int e = beg;
    for (; e + 2 <= end; e += 2) {
        int s0 = col[e], s1 = col[e + 1];
        float4 xA = *(const float4*)(xl + (size_t)s0 * H + lane * 4);
        float4 xB = *(const float4*)(xl + (size_t)s1 * H + lane * 4);

        float eA0 = xA.x + xr4.x; eA0 = (eA0 > 0.f) ? eA0 : 0.2f * eA0;
        float eA1 = xA.y + xr4.y; eA1 = (eA1 > 0.f) ? eA1 : 0.2f * eA1;
        float eA2 = xA.z + xr4.z; eA2 = (eA2 > 0.f) ? eA2 : 0.2f * eA2;
        float eA3 = xA.w + xr4.w; eA3 = (eA3 > 0.f) ? eA3 : 0.2f * eA3;
        float pA = eA0 * at4.x + eA1 * at4.y + eA2 * at4.z + eA3 * at4.w;

        float eB0 = xB.x + xr4.x; eB0 = (eB0 > 0.f) ? eB0 : 0.2f * eB0;
        float eB1 = xB.y + xr4.y; eB1 = (eB1 > 0.f) ? eB1 : 0.2f * eB1;
        float eB2 = xB.z + xr4.z; eB2 = (eB2 > 0.f) ? eB2 : 0.2f * eB2;
        float eB3 = xB.w + xr4.w; eB3 = (eB3 > 0.f) ? eB3 : 0.2f * eB3;
        float pB = eB0 * at4.x + eB1 * at4.y + eB2 * at4.z + eB3 * at4.w;

#pragma unroll
        for (int off = 8; off > 0; off >>= 1) {
            pA += __shfl_xor_sync(0xffffffffu, pA, off);
            pB += __shfl_xor_sync(0xffffffffu, pB, off);
        }
        float peA = expf(pA);
        float peB = expf(pB);
        den += peA + peB;
        a0 += peA * xA.x + peB * xB.x;
        a1 += peA * xA.y + peB * xB.y;
        a2 += peA * xA.z + peB * xB.z;
        a3 += peA * xA.w + peB * xB.w;
    }
    if (e < end) {
        int s0 = col[e];
        float4 xA = *(const float4*)(xl + (size_t)s0 * H + lane * 4);
        float eA0 = xA.x + xr4.x; eA0 = (eA0 > 0.f) ? eA0 : 0.2f * eA0;
        float eA1 = xA.y + xr4.y; eA1 = (eA1 > 0.f) ? eA1 : 0.2f * eA1;
        float eA2 = xA.z + xr4.z; eA2 = (eA2 > 0.f) ? eA2 : 0.2f * eA2;
        float eA3 = xA.w + xr4.w; eA3 = (eA3 > 0.f) ? eA3 : 0.2f * eA3;
        float pA = eA0 * at4.x + eA1 * at4.y + eA2 * at4.z + eA3 * at4.w;
#pragma unroll
        for (int off = 8; off > 0; off >>= 1)
            pA += __shfl_xor_sync(0xffffffffu, pA, off);
        float peA = expf(pA);
        den += peA;
        a0 += peA * xA.x;
        a1 += peA * xA.y;
        a2 += peA * xA.z;
        a3 += peA * xA.w;
    }

    float inv = 1.f / (den + 1e-16f);
    float4 r;
    r.x = a0 * inv + b4.x;
    r.y = a1 * inv + b4.y;
    r.z = a2 * inv + b4.z;
    r.w = a3 * inv + b4.w;
    if (roundOut) {
        r.x = rndtf32(r.x); r.y = rndtf32(r.y);
        r.z = rndtf32(r.z); r.w = rndtf32(r.w);
    }
    *(float4*)o = r;
}

extern "C" void kernel_launch(void* const* d_in, const int* in_sizes, int n_in,
                              void* d_out, int out_size)
{
    const float* x_user  = (const float*)d_in[0];
    const float* x_item  = (const float*)d_in[1];
    const float* Wp_user = (const float*)d_in[2];
    const float* bp_user = (const float*)d_in[3];
    const float* Wp_item = (const float*)d_in[4];
    const float* bp_item = (const float*)d_in[5];
    const float* Wl      = (const float*)d_in[6];
    const float* bl      = (const float*)d_in[7];
    const float* Wr      = (const float*)d_in[8];
    const float* br      = (const float*)d_in[9];
    const float* att     = (const float*)d_in[10];
    const float* bias    = (const float*)d_in[11];
    const int*   e_src   = (const int*)d_in[12];
    const int*   e_dst   = (const int*)d_in[13];
    const int    nE      = in_sizes[12];

    float* out = (float*)d_out;

    float *zu, *zi, *zu2, *zi2, *xlu, *xru, *xli, *xri, *wtf;
    int *rp_i, *rp_u, *cnt_i, *cnt_u, *col_i, *col_u, *bs_i, *bs_u;
    cudaGetSymbolAddress((void**)&zu,  g_zu);
    cudaGetSymbolAddress((void**)&zi,  g_zi);
    cudaGetSymbolAddress((void**)&zu2, g_zu2);
    cudaGetSymbolAddress((void**)&zi2, g_zi2);
    cudaGetSymbolAddress((void**)&xlu, g_xlu);
    cudaGetSymbolAddress((void**)&xru, g_xru);
    cudaGetSymbolAddress((void**)&xli, g_xli);
    cudaGetSymbolAddress((void**)&xri, g_xri);
    cudaGetSymbolAddress((void**)&wtf, g_wtf);
    cudaGetSymbolAddress((void**)&rp_i,  g_rp_i);
    cudaGetSymbolAddress((void**)&rp_u,  g_rp_u);
    cudaGetSymbolAddress((void**)&cnt_i, g_cnt_i);
    cudaGetSymbolAddress((void**)&cnt_u, g_cnt_u);
    cudaGetSymbolAddress((void**)&col_i, g_col_i);
    cudaGetSymbolAddress((void**)&col_u, g_col_u);
    cudaGetSymbolAddress((void**)&bs_i,  g_bsum_i);
    cudaGetSymbolAddress((void**)&bs_u,  g_bsum_u);

    cudaFuncSetAttribute(gemm_fused, cudaFuncAttributeMaxDynamicSharedMemorySize, SMEM_BYTES);

    cudaStream_t st = 0;
    const int UB = (NU + BM - 1) / BM;
    const int IB = (NI + BM - 1) / BM;
    const int NB_I = (NI + 4095) / 4096;   // 5
    const int NB_U = (NU + 4095) / 4096;   // 25

    // ---- pre-round weights to tf32 (bit-identical to per-tile rounding) ----
    round_w<<<(W_TOT + 255) / 256, 256, 0, st>>>(Wp_user, Wp_item, Wl, Wr, wtf);

    // ---- CSR build (graph shared by both layers) ----
    zero_counts<<<(NU + 255) / 256, 256, 0, st>>>(cnt_i, cnt_u);
    build_hist<<<(nE + 255) / 256, 256, 0, st>>>(e_src, e_dst, cnt_u, cnt_i, nE);
    scan_p1_both<<<NB_I + NB_U, 1024, 0, st>>>(cnt_i, bs_i, NB_I, NI, cnt_u, bs_u, NU);
    scan_p2_both<<<1, 64, 0, st>>>(bs_i, NB_I, rp_i, NI, bs_u, NB_U, rp_u, NU);
    scan_p3_both<<<NB_I + NB_U, 1024, 0, st>>>(cnt_i, bs_i, NB_I, rp_i, cnt_i, NI,
                                               cnt_u, bs_u, rp_u, cnt_u, NU);
    fill_csr<<<(nE + 255) / 256, 256, 0, st>>>(e_src, e_dst, cnt_u, cnt_i, col_u, col_i, nE);

    // ---- input projections (raw A -> cvtA=1; outputs feed only GEMM A -> roundC=1) ----
    {
        dim3 grid(1, UB + IB);
        gemm_fused<<<grid, 256, SMEM_BYTES, st>>>(
            x_user, NU, 64, x_item, NI, 128, UB,
            wtf + WO_PU, bp_user, zu,  wtf + WO_PU, bp_user, zu,
            wtf + WO_PI, bp_item, zi,  wtf + WO_PI, bp_item, zi,
            0, 1, 1);
    }

    const int GBLK = ((NI + NU) * 32 + 255) / 256;

    for (int l = 0; l < 2; l++) {
        const float* inU = (l == 0) ? zu : zu2;
        const float* inI = (l == 0) ? zi : zi2;
        float* outU = (l == 0) ? zu2 : out;
        float* outI = (l == 0) ? zi2 : out + (size_t)NU * H;

        int r0 = l * 2 + 0;
        int r1 = l * 2 + 1;

        {
            dim3 grid(2, UB + IB);
            gemm_fused<<<grid, 256, SMEM_BYTES, st>>>(
                inU, NU, H, inI, NI, H, UB,
                wtf + WO_WL + (size_t)r0 * 16384, bl + (size_t)r0 * H, xlu,
                wtf + WO_WR + (size_t)r1 * 16384, br + (size_t)r1 * H, xru,
                wtf + WO_WR + (size_t)r0 * 16384, br + (size_t)r0 * H, xri,
                wtf + WO_WL + (size_t)r1 * 16384, bl + (size_t)r1 * H, xli,
                (l == 1) ? 1 : 0, 0, 0);
        }

        gat_gather<<<GBLK, 256, 0, st>>>(
            xlu, xri, att + (size_t)r0 * H, bias + (size_t)r0 * H, outI,
            xli, xru, att + (size_t)r1 * H, bias + (size_t)r1 * H, outU,
            rp_i, col_i, rp_u, col_u,
            (l == 0) ? 1 : 0);
    }
}

// round 8
// speedup vs baseline: 3.7699x; 1.0342x over previous
#include <cuda_runtime.h>
#include <cstdint>

#define NU 100000
#define NI 20000
#define NE 250000
#define H  128
#define HEADS 2
#define D  64

// ---------------- scratch (static device arrays; no allocation) ----------------
__device__ float g_zu [NU * H];
__device__ float g_zi [NI * H];
__device__ float g_zu2[NU * H];
__device__ float g_zi2[NI * H];
__device__ float g_xlu[NU * H];
__device__ float g_xru[NU * H];
__device__ float g_xli[NI * H];
__device__ float g_xri[NI * H];
__device__ float g_wtf[155648];     // tf32-rounded weights

// CSR (built once per call; graph identical across layers)
__device__ int g_rp_i [NI + 1];
__device__ int g_rp_u [NU + 1];
__device__ int g_cnt_i[NI];
__device__ int g_cnt_u[NU];
__device__ int g_col_i[NE];
__device__ int g_col_u[NE];
__device__ int g_bsum_i[32];
__device__ int g_bsum_u[32];

// ---------------- tf32 helpers -------------------------------------------------
__device__ __forceinline__ uint32_t f2tf32(float x) {
    uint32_t u;
    asm("cvt.rna.tf32.f32 %0, %1;" : "=r"(u) : "f"(x));
    return u;
}
__device__ __forceinline__ float rndtf32(float x) {
    return __uint_as_float(f2tf32(x));
}

// pre-round all weight matrices once per call
#define WO_PU 0
#define WO_PI 8192
#define WO_WL 24576
#define WO_WR 90112
#define W_TOT 155648
__global__ void round_w(const float* __restrict__ pu, const float* __restrict__ pi,
                        const float* __restrict__ wl, const float* __restrict__ wr,
                        float* __restrict__ o) {
    int i = blockIdx.x * blockDim.x + threadIdx.x;
    float v;
    if (i < WO_PI) v = pu[i];
    else if (i < WO_WL) v = pi[i - WO_PI];
    else if (i < WO_WR) v = wl[i - WO_WL];
    else if (i < W_TOT) v = wr[i - WO_WR];
    else return;
    o[i] = rndtf32(v);
}

// ---------------- tf32 tensor-core GEMM, cp.async 2-stage pipeline -------------
#define BM 128
#define BN 128
#define BK 32
#define AST 36
#define BST 136
#define SMEM_BYTES ((2*BM*AST + 2*BK*BST) * 4)

template<int N> struct IC { static constexpr int v = N; };

__device__ __forceinline__ void cp16(uint32_t dst, const float* src, bool pred) {
    asm volatile("cp.async.ca.shared.global [%0], [%1], 16, %2;"
                 :: "r"(dst), "l"(src), "r"(pred ? 16 : 0));
}

template<int KTU, int KTI>
__global__ __launch_bounds__(256, 2) void gemm_fused(
    const float* __restrict__ Au, int Mu, int Ku,
    const float* __restrict__ Ai, int Mi, int Ki, int UB,
    const float* __restrict__ W00, const float* __restrict__ b00, float* __restrict__ C00,
    const float* __restrict__ W01, const float* __restrict__ b01, float* __restrict__ C01,
    const float* __restrict__ W10, const float* __restrict__ b10, float* __restrict__ C10,
    const float* __restrict__ W11, const float* __restrict__ b11, float* __restrict__ C11,
    int reluA, int cvtA, int roundC)
{
    extern __shared__ float smbuf[];
    const int sec = (blockIdx.y >= (unsigned)UB) ? 1 : 0;
    const float* A = sec ? Ai : Au;
    const int M = sec ? Mi : Mu;
    const int K = sec ? Ki : Ku;
    const int bm = (sec ? (blockIdx.y - UB) : blockIdx.y) * BM;

    const float* W; const float* bv; float* C;
    if (!sec) { if (blockIdx.x == 0) { W=W00; bv=b00; C=C00; } else { W=W01; bv=b01; C=C01; } }
    else      { if (blockIdx.x == 0) { W=W10; bv=b10; C=C10; } else { W=W11; bv=b11; C=C11; } }

    const int tid  = threadIdx.x;
    const int lane = tid & 31;
    const int warp = tid >> 5;
    const int wm   = warp >> 2;
    const int wn   = warp & 3;

    float* As = smbuf;
    float* Bs = smbuf + 2 * BM * AST;

    const int arow = tid >> 3;
    const int acol = (tid & 7) * 4;
    const int brow = tid >> 5;
    const int bcol = (tid & 31) * 4;

    float acc[4][4][4];
#pragma unroll
    for (int mt = 0; mt < 4; mt++)
#pragma unroll
        for (int nt = 0; nt < 4; nt++)
#pragma unroll
            for (int c = 0; c < 4; c++) acc[mt][nt][c] = 0.f;

    auto stage = [&](int kt, int buf) {
#pragma unroll
        for (int i = 0; i < 4; i++) {
            int row = arow + 32 * i;
            bool p = (bm + row) < M;
            int r = p ? (bm + row) : (M - 1);
            uint32_t d = (uint32_t)__cvta_generic_to_shared(As + buf * BM * AST + row * AST + acol);
            cp16(d, A + (size_t)r * K + kt * BK + acol, p);
        }
#pragma unroll
        for (int i = 0; i < 4; i++) {
            int kr = brow + 8 * i;
            uint32_t d = (uint32_t)__cvta_generic_to_shared(Bs + buf * BK * BST + kr * BST + bcol);
            cp16(d, W + (size_t)(kt * BK + kr) * BN + bcol, true);
        }
    };

    auto compute = [&](int buf) {
        const float* Asb = As + buf * BM * AST;
        const float* Bsb = Bs + buf * BK * BST;
#pragma unroll
        for (int kk = 0; kk < 4; kk++) {
            uint32_t a[4][4];
            {
                int row  = wm * 64 + (lane & 15);
                int koff = kk * 8 + ((lane >> 4) << 2);
#pragma unroll
                for (int mt = 0; mt < 4; mt++) {
                    uint32_t sa = (uint32_t)__cvta_generic_to_shared(
                        Asb + (row + mt * 16) * AST + koff);
                    asm volatile(
                        "ldmatrix.sync.aligned.m8n8.x4.shared.b16 {%0,%1,%2,%3}, [%4];"
                        : "=r"(a[mt][0]), "=r"(a[mt][1]), "=r"(a[mt][2]), "=r"(a[mt][3])
                        : "r"(sa));
                }
            }
            if (reluA) {
#pragma unroll
                for (int mt = 0; mt < 4; mt++)
#pragma unroll
                    for (int i = 0; i < 4; i++)
                        a[mt][i] = __float_as_uint(fmaxf(__uint_as_float(a[mt][i]), 0.f));
            }
            if (cvtA) {
#pragma unroll
                for (int mt = 0; mt < 4; mt++)
#pragma unroll
                    for (int i = 0; i < 4; i++)
                        a[mt][i] = f2tf32(__uint_as_float(a[mt][i]));
            }

            uint32_t b[4][2];
            {
                int kb = kk * 8 + (lane & 3);
                int nb = wn * 32 + (lane >> 2);
#pragma unroll
                for (int nt = 0; nt < 4; nt++) {
                    b[nt][0] = __float_as_uint(Bsb[kb * BST + nb + nt * 8]);
                    b[nt][1] = __float_as_uint(Bsb[(kb + 4) * BST + nb + nt * 8]);
                }
            }
#pragma unroll
            for (int mt = 0; mt < 4; mt++)
#pragma unroll
                for (int nt = 0; nt < 4; nt++) {
                    asm volatile(
                        "mma.sync.aligned.m16n8k8.row.col.f32.tf32.tf32.f32 "
                        "{%0,%1,%2,%3}, {%4,%5,%6,%7}, {%8,%9}, {%0,%1,%2,%3};"
                        : "+f"(acc[mt][nt][0]), "+f"(acc[mt][nt][1]),
                          "+f"(acc[mt][nt][2]), "+f"(acc[mt][nt][3])
                        : "r"(a[mt][0]), "r"(a[mt][1]), "r"(a[mt][2]), "r"(a[mt][3]),
                          "r"(b[nt][0]), "r"(b[nt][1]));
                }
        }
    };

    // mainloop with compile-time tile count (fully unrolled)
    auto run = [&](auto ktc) {
        constexpr int KT = decltype(ktc)::v;
        stage(0, 0);
        asm volatile("cp.async.commit_group;");
#pragma unroll
        for (int kt = 0; kt < KT; kt++) {
            int buf = kt & 1;
            if (kt + 1 < KT) {
                stage(kt + 1, buf ^ 1);
                asm volatile("cp.async.commit_group;");
                asm volatile("cp.async.wait_group 1;");
            } else {
                asm volatile("cp.async.wait_group 0;");
            }
            __syncthreads();
            compute(buf);
            __syncthreads();
        }
    };
    if (sec == 0) run(IC<KTU>{});
    else          run(IC<KTI>{});

    const int r0 = bm + wm * 64 + (lane >> 2);
    const int cb = wn * 32 + 2 * (lane & 3);
#pragma unroll
    for (int mt = 0; mt < 4; mt++) {
#pragma unroll
        for (int nt = 0; nt < 4; nt++) {
            int row = r0 + mt * 16;
            int col = cb + nt * 8;
            float bx = bv[col], by = bv[col + 1];
            if (row < M) {
                float2 v = make_float2(acc[mt][nt][0] + bx, acc[mt][nt][1] + by);
                if (roundC) { v.x = rndtf32(v.x); v.y = rndtf32(v.y); }
                *(float2*)(C + (size_t)row * BN + col) = v;
            }
            if (row + 8 < M) {
                float2 v = make_float2(acc[mt][nt][2] + bx, acc[mt][nt][3] + by);
                if (roundC) { v.x = rndtf32(v.x); v.y = rndtf32(v.y); }
                *(float2*)(C + (size_t)(row + 8) * BN + col) = v;
            }
        }
    }
}

// ---------------- CSR construction (once per call) -----------------------------
__global__ void zero_counts(int* __restrict__ ci, int* __restrict__ cu) {
    int i = blockIdx.x * blockDim.x + threadIdx.x;
    if (i < NI) ci[i] = 0;
    if (i < NU) cu[i] = 0;
}

__global__ void build_hist(const int* __restrict__ es, const int* __restrict__ ed,
                           int* __restrict__ cu, int* __restrict__ ci, int nE) {
    int i = blockIdx.x * blockDim.x + threadIdx.x;
    if (i < nE) {
        atomicAdd(ci + ed[i], 1);
        atomicAdd(cu + es[i], 1);
    }
}

__global__ __launch_bounds__(1024) void scan_p1_both(
    const int* __restrict__ ci, int* __restrict__ bi, int nbi, int ni,
    const int* __restrict__ cu, int* __restrict__ bu, int nu)
{
    __shared__ int sh[1024];
    const int* cnt; int* bsums; int n; int blk;
    if ((int)blockIdx.x < nbi) { cnt = ci; bsums = bi; n = ni; blk = blockIdx.x; }
    else { cnt = cu; bsums = bu; n = nu; blk = blockIdx.x - nbi; }
    int base = blk * 4096;
    int t = threadIdx.x;
    int s = 0;
#pragma unroll
    for (int j = 0; j < 4; j++) {
        int i = base + t * 4 + j;
        if (i < n) s += cnt[i];
    }
    sh[t] = s;
    __syncthreads();
    for (int d = 512; d > 0; d >>= 1) {
        if (t < d) sh[t] += sh[t + d];
        __syncthreads();
    }
    if (t == 0) bsums[blk] = sh[0];
}

__global__ void scan_p2_both(int* __restrict__ bi, int nbi, int* __restrict__ rpi, int ni,
                             int* __restrict__ bu, int nbu, int* __restrict__ rpu, int nu) {
    int w = threadIdx.x >> 5;
    int t = threadIdx.x & 31;
    int* bs = w ? bu : bi;
    int nb = w ? nbu : nbi;
    int* rp = w ? rpu : rpi;
    int n  = w ? nu : ni;
    int own = (t < nb) ? bs[t] : 0;
    int v = own;
#pragma unroll
    for (int d = 1; d < 32; d <<= 1) {
        int u = __shfl_up_sync(0xffffffffu, v, d);
        if (t >= d) v += u;
    }
    if (t < nb) bs[t] = v - own;
    if (t == nb - 1) rp[n] = v;
}

__global__ __launch_bounds__(1024) void scan_p3_both(
    const int* __restrict__ ci, const int* __restrict__ bi, int nbi,
    int* __restrict__ rpi, int* __restrict__ curi, int ni,
    const int* __restrict__ cu, const int* __restrict__ bu,
    int* __restrict__ rpu, int* __restrict__ curu, int nu)
{
    __shared__ int sh[1024];
    const int* cnt; const int* bsums; int* rp; int* cur; int n; int blk;
    if ((int)blockIdx.x < nbi) { cnt = ci; bsums = bi; rp = rpi; cur = curi; n = ni; blk = blockIdx.x; }
    else { cnt = cu; bsums = bu; rp = rpu; cur = curu; n = nu; blk = blockIdx.x - nbi; }
    int base = blk * 4096;
    int t = threadIdx.x;
    int c[4];
    int s = 0;
#pragma unroll
    for (int j = 0; j < 4; j++) {
        int i = base + t * 4 + j;
        c[j] = (i < n) ? cnt[i] : 0;
        s += c[j];
    }
    sh[t] = s;
    __syncthreads();
    for (int d = 1; d < 1024; d <<= 1) {
        int v = (t >= d) ? sh[t - d] : 0;
        __syncthreads();
        sh[t] += v;
        __syncthreads();
    }
    int off = bsums[blk] + ((t > 0) ? sh[t - 1] : 0);
#pragma unroll
    for (int j = 0; j < 4; j++) {
        int i = base + t * 4 + j;
        if (i < n) {
            rp[i] = off;
            cur[i] = off;
            off += c[j];
        }
    }
}

__global__ void fill_csr(const int* __restrict__ es, const int* __restrict__ ed,
                         int* __restrict__ cur_u, int* __restrict__ cur_i,
                         int* __restrict__ col_u, int* __restrict__ col_i, int nE) {
    int i = blockIdx.x * blockDim.x + threadIdx.x;
    if (i < nE) {
        int s = es[i], t = ed[i];
        col_i[atomicAdd(cur_i + t, 1)] = s;
        col_u[atomicAdd(cur_u + s, 1)] = t;
    }
}

// ---------------- fused GATv2 gather (both relations of one layer) -------------
__global__ __launch_bounds__(256) void gat_gather(
    const float* __restrict__ xlu, const float* __restrict__ xri,
    const float* __restrict__ att0, const float* __restrict__ bias0,
    float* __restrict__ outI,
    const float* __restrict__ xli, const float* __restrict__ xru,
    const float* __restrict__ att1, const float* __restrict__ bias1,
    float* __restrict__ outU,
    const int* __restrict__ rp_i, const int* __restrict__ col_i,
    const int* __restrict__ rp_u, const int* __restrict__ col_u,
    int roundOut)
{
    int w = (blockIdx.x * blockDim.x + threadIdx.x) >> 5;
    int lane = threadIdx.x & 31;

    const float* xl; const float* xr; const float* att; const float* bias;
    float* out; const int* rp; const int* col; int t;
    if (w < NI) {
        t = w; xl = xlu; xr = xri; att = att0; bias = bias0; out = outI;
        rp = rp_i; col = col_i;
    } else if (w < NI + NU) {
        t = w - NI; xl = xli; xr = xru; att = att1; bias = bias1; out = outU;
        rp = rp_u; col = col_u;
    } else return;

    int beg = rp[t], end = rp[t + 1];
    float4 b4 = *(const float4*)(bias + lane * 4);
    float* o = out + (size_t)t * H + lane * 4;

    if (beg == end) {
        if (roundOut) {
            b4.x = rndtf32(b4.x); b4.y = rndtf32(b4.y);
            b4.z = rndtf32(b4.z); b4.w = rndtf32(b4.w);
        }
        *(float4*)o = b4;
        return;
    }

    float4 xr4 = *(const float4*)(xr + (size_t)t * H + lane * 4);
    float4 at4 = *(const float4*)(att + lane * 4);

    float a0 = 0.f, a1 = 0.f, a2 = 0.f, a3 = 0.f, den = 0.f;

    int e = beg;
    for (; e + 2 <= end; e += 2) {
        int s0 = col[e], s1 = col[e + 1];
        float4 xA = *(const float4*)(xl + (size_t)s0 * H + lane * 4);
        float4 xB = *(const float4*)(xl + (size_t)s1 * H + lane * 4);

        float eA0 = xA.x + xr4.x; eA0 = (eA0 > 0.f) ? eA0 : 0.2f * eA0;
        float eA1 = xA.y + xr4.y; eA1 = (eA1 > 0.f) ? eA1 : 0.2f * eA1;
        float eA2 = xA.z + xr4.z; eA2 = (eA2 > 0.f) ? eA2 : 0.2f * eA2;
        float eA3 = xA.w + xr4.w; eA3 = (eA3 > 0.f) ? eA3 : 0.2f * eA3;
        float pA = eA0 * at4.x + eA1 * at4.y + eA2 * at4.z + eA3 * at4.w;

        float eB0 = xB.x + xr4.x; eB0 = (eB0 > 0.f) ? eB0 : 0.2f * eB0;
        float eB1 = xB.y + xr4.y; eB1 = (eB1 > 0.f) ? eB1 : 0.2f * eB1;
        float eB2 = xB.z + xr4.z; eB2 = (eB2 > 0.f) ? eB2 : 0.2f * eB2;
        float eB3 = xB.w + xr4.w; eB3 = (eB3 > 0.f) ? eB3 : 0.2f * eB3;
        float pB = eB0 * at4.x + eB1 * at4.y + eB2 * at4.z + eB3 * at4.w;

#pragma unroll
        for (int off = 8; off > 0; off >>= 1) {
            pA += __shfl_xor_sync(0xffffffffu, pA, off);
            pB += __shfl_xor_sync(0xffffffffu, pB, off);
        }
        float peA = expf(pA);
        float peB = expf(pB);
        den += peA + peB;
        a0 += peA * xA.x + peB * xB.x;
        a1 += peA * xA.y + peB * xB.y;
        a2 += peA * xA.z + peB * xB.z;
        a3 += peA * xA.w + peB * xB.w;
    }
    if (e < end) {
        int s0 = col[e];
        float4 xA = *(const float4*)(xl + (size_t)s0 * H + lane * 4);
        float eA0 = xA.x + xr4.x; eA0 = (eA0 > 0.f) ? eA0 : 0.2f * eA0;
        float eA1 = xA.y + xr4.y; eA1 = (eA1 > 0.f) ? eA1 : 0.2f * eA1;
        float eA2 = xA.z + xr4.z; eA2 = (eA2 > 0.f) ? eA2 : 0.2f * eA2;
        float eA3 = xA.w + xr4.w; eA3 = (eA3 > 0.f) ? eA3 : 0.2f * eA3;
        float pA = eA0 * at4.x + eA1 * at4.y + eA2 * at4.z + eA3 * at4.w;
#pragma unroll
        for (int off = 8; off > 0; off >>= 1)
            pA += __shfl_xor_sync(0xffffffffu, pA, off);
        float peA = expf(pA);
        den += peA;
        a0 += peA * xA.x;
        a1 += peA * xA.y;
        a2 += peA * xA.z;
        a3 += peA * xA.w;
    }

    float inv = 1.f / (den + 1e-16f);
    float4 r;
    r.x = a0 * inv + b4.x;
    r.y = a1 * inv + b4.y;
    r.z = a2 * inv + b4.z;
    r.w = a3 * inv + b4.w;
    if (roundOut) {
        r.x = rndtf32(r.x); r.y = rndtf32(r.y);
        r.z = rndtf32(r.z); r.w = rndtf32(r.w);
    }
    *(float4*)o = r;
}

extern "C" void kernel_launch(void* const* d_in, const int* in_sizes, int n_in,
                              void* d_out, int out_size)
{
    const float* x_user  = (const float*)d_in[0];
    const float* x_item  = (const float*)d_in[1];
    const float* Wp_user = (const float*)d_in[2];
    const float* bp_user = (const float*)d_in[3];
    const float* Wp_item = (const float*)d_in[4];
    const float* bp_item = (const float*)d_in[5];
    const float* Wl      = (const float*)d_in[6];
    const float* bl      = (const float*)d_in[7];
    const float* Wr      = (const float*)d_in[8];
    const float* br      = (const float*)d_in[9];
    const float* att     = (const float*)d_in[10];
    const float* bias    = (const float*)d_in[11];
    const int*   e_src   = (const int*)d_in[12];
    const int*   e_dst   = (const int*)d_in[13];
    const int    nE      = in_sizes[12];

    float* out = (float*)d_out;

    float *zu, *zi, *zu2, *zi2, *xlu, *xru, *xli, *xri, *wtf;
    int *rp_i, *rp_u, *cnt_i, *cnt_u, *col_i, *col_u, *bs_i, *bs_u;
    cudaGetSymbolAddress((void**)&zu,  g_zu);
    cudaGetSymbolAddress((void**)&zi,  g_zi);
    cudaGetSymbolAddress((void**)&zu2, g_zu2);
    cudaGetSymbolAddress((void**)&zi2, g_zi2);
    cudaGetSymbolAddress((void**)&xlu, g_xlu);
    cudaGetSymbolAddress((void**)&xru, g_xru);
    cudaGetSymbolAddress((void**)&xli, g_xli);
    cudaGetSymbolAddress((void**)&xri, g_xri);
    cudaGetSymbolAddress((void**)&wtf, g_wtf);
    cudaGetSymbolAddress((void**)&rp_i,  g_rp_i);
    cudaGetSymbolAddress((void**)&rp_u,  g_rp_u);
    cudaGetSymbolAddress((void**)&cnt_i, g_cnt_i);
    cudaGetSymbolAddress((void**)&cnt_u, g_cnt_u);
    cudaGetSymbolAddress((void**)&col_i, g_col_i);
    cudaGetSymbolAddress((void**)&col_u, g_col_u);
    cudaGetSymbolAddress((void**)&bs_i,  g_bsum_i);
    cudaGetSymbolAddress((void**)&bs_u,  g_bsum_u);

    cudaFuncSetAttribute(gemm_fused<2,4>, cudaFuncAttributeMaxDynamicSharedMemorySize, SMEM_BYTES);
    cudaFuncSetAttribute(gemm_fused<4,4>, cudaFuncAttributeMaxDynamicSharedMemorySize, SMEM_BYTES);

    // side stream + events (created once, before graph capture begins;
    // fork/join via events is the capture-legal branching pattern)
    static cudaStream_t s2 = nullptr;
    static cudaEvent_t evFork = nullptr, evJoin = nullptr;
    if (s2 == nullptr) {
        cudaStreamCreateWithFlags(&s2, cudaStreamNonBlocking);
        cudaEventCreateWithFlags(&evFork, cudaEventDisableTiming);
        cudaEventCreateWithFlags(&evJoin, cudaEventDisableTiming);
    }

    cudaStream_t st = 0;
    const int UB = (NU + BM - 1) / BM;
    const int IB = (NI + BM - 1) / BM;
    const int NB_I = (NI + 4095) / 4096;
    const int NB_U = (NU + 4095) / 4096;

    // ---- fork: CSR build on side stream, overlapped with weight-round+GEMMs ----
    cudaEventRecord(evFork, st);
    cudaStreamWaitEvent(s2, evFork, 0);

    zero_counts<<<(NU + 255) / 256, 256, 0, s2>>>(cnt_i, cnt_u);
    build_hist<<<(nE + 255) / 256, 256, 0, s2>>>(e_src, e_dst, cnt_u, cnt_i, nE);
    scan_p1_both<<<NB_I + NB_U, 1024, 0, s2>>>(cnt_i, bs_i, NB_I, NI, cnt_u, bs_u, NU);
    scan_p2_both<<<1, 64, 0, s2>>>(bs_i, NB_I, rp_i, NI, bs_u, NB_U, rp_u, NU);
    scan_p3_both<<<NB_I + NB_U, 1024, 0, s2>>>(cnt_i, bs_i, NB_I, rp_i, cnt_i, NI,
                                               cnt_u, bs_u, rp_u, cnt_u, NU);
    fill_csr<<<(nE + 255) / 256, 256, 0, s2>>>(e_src, e_dst, cnt_u, cnt_i, col_u, col_i, nE);
    cudaEventRecord(evJoin, s2);

    // ---- main stream: weights + projections ----
    round_w<<<(W_TOT + 255) / 256, 256, 0, st>>>(Wp_user, Wp_item, Wl, Wr, wtf);
    {
        dim3 grid(1, UB + IB);
        gemm_fused<2,4><<<grid, 256, SMEM_BYTES, st>>>(
            x_user, NU, 64, x_item, NI, 128, UB,
            wtf + WO_PU, bp_user, zu,  wtf + WO_PU, bp_user, zu,
            wtf + WO_PI, bp_item, zi,  wtf + WO_PI, bp_item, zi,
            0, 1, 1);
    }

    const int GBLK = ((NI + NU) * 32 + 255) / 256;
    bool joined = false;

    for (int l = 0; l < 2; l++) {
        const float* inU = (l == 0) ? zu : zu2;
        const float* inI = (l == 0) ? zi : zi2;
        float* outU = (l == 0) ? zu2 : out;
        float* outI = (l == 0) ? zi2 : out + (size_t)NU * H;

        int r0 = l * 2 + 0;
        int r1 = l * 2 + 1;

        {
            dim3 grid(2, UB + IB);
            gemm_fused<4,4><<<grid, 256, SMEM_BYTES, st>>>(
                inU, NU, H, inI, NI, H, UB,
                wtf + WO_WL + (size_t)r0 * 16384, bl + (size_t)r0 * H, xlu,
                wtf + WO_WR + (size_t)r1 * 16384, br + (size_t)r1 * H, xru,
                wtf + WO_WR + (size_t)r0 * 16384, br + (size_t)r0 * H, xri,
                wtf + WO_WL + (size_t)r1 * 16384, bl + (size_t)r1 * H, xli,
                (l == 1) ? 1 : 0, 0, 0);
        }

        if (!joined) {   // CSR must be ready before the first gather
            cudaStreamWaitEvent(st, evJoin, 0);
            joined = true;
        }

        gat_gather<<<GBLK, 256, 0, st>>>(
            xlu, xri, att + (size_t)r0 * H, bias + (size_t)r0 * H, outI,
            xli, xru, att + (size_t)r1 * H, bias + (size_t)r1 * H, outU,
            rp_i, col_i, rp_u, col_u,
            (l == 0) ? 1 : 0);
    }
}